// round 14
// baseline (speedup 1.0000x reference)
#include <cuda_runtime.h>
#include <math.h>

#define NPTS 2048
#define DIN  768
#define DOUT 64
#define NMAT 7
#define NCHUNK 16                      // 128-column chunks per row
#define LN_N   7.624618986159398f      // ln(2048)
#define LOG2E  1.4426950408889634f
#define LN2    0.6931471805599453f
#define SKIP_MARGIN 26.0f              // skip chunk if ub < mglob - 26 (2^-26)
#define SKIP_START 16                  // first step with V maintenance

// ---------------------------------------------------------------------------
// Device scratch (static globals — no allocation in kernel_launch)
// ---------------------------------------------------------------------------
__device__ __align__(16) float d_Wt[DIN * DOUT];             // W^T: [768][64]
__device__ __align__(16) float d_P[3][NPTS * DOUT];          // pd, p1, p2
__device__ __align__(16) float d_SQ[3][NPTS];                // 0.5*||row||^2
__device__ __align__(16) float d_C[NMAT][(size_t)NPTS * NPTS];
// 0:Cxx 1:C11 2:C22 3:Cxy1 4:Cyx1 5:Cxy2 6:Cyx2
__device__ __align__(16) float d_pot[2][7][NPTS];            // ping-pong potentials
// slots: 0:f_xx 1:f_11 2:f_22 3:f_xy1 4:g_xy1 5:f_xy2 6:g_xy2
__device__ __align__(16) float d_potF[7][NPTS];              // final potentials
__device__ __align__(16) float d_V[NMAT][NPTS][NCHUNK];      // min_j∈c (C_ij - g_j)
__device__ __align__(16) float d_prev[2][NMAT][NPTS];        // vin snapshots (2-buf)

__constant__ int cAi[5] = {0, 1, 2, 0, 0};
__constant__ int cBi[5] = {0, 1, 2, 1, 2};
__constant__ int cCi[5] = {0, 1, 2, 3, 5};
__constant__ int cTi[5] = {-1, -1, -1, 4, 6};

__device__ __forceinline__ float ex2f(float x) {
    float r; asm("ex2.approx.ftz.f32 %0, %1;" : "=f"(r) : "f"(x)); return r;
}
__device__ __forceinline__ float lg2f(float x) {
    float r; asm("lg2.approx.f32 %0, %1;" : "=f"(r) : "f"(x)); return r;
}

// ---------------------------------------------------------------------------
// W transpose:  Wt[j][k] = W[k][j]
// ---------------------------------------------------------------------------
__global__ void k_transposeW(const float* __restrict__ W) {
    int e = blockIdx.x * blockDim.x + threadIdx.x;
    if (e < DIN * DOUT) {
        int j = e / DOUT, k = e % DOUT;
        d_Wt[e] = W[k * DIN + j];
    }
}

// ---------------------------------------------------------------------------
// predict: P = relu(X @ W^T + b). 64x64 tile / 256 threads.
// ---------------------------------------------------------------------------
__global__ __launch_bounds__(256) void k_predict(const float* __restrict__ X0,
                                                 const float* __restrict__ X1,
                                                 const float* __restrict__ X2,
                                                 const float* __restrict__ bias) {
    __shared__ __align__(16) float Xs[64 * 68];   // [kk][row]
    __shared__ __align__(16) float Ws[64 * 64];   // [kk][col]
    const float* X = (blockIdx.y == 0) ? X0 : (blockIdx.y == 1) ? X1 : X2;
    int rowBase = blockIdx.x * 64;
    int tid = threadIdx.x;
    int ty = tid >> 4, tx = tid & 15;

    float acc[4][4];
#pragma unroll
    for (int i = 0; i < 4; i++)
#pragma unroll
        for (int j = 0; j < 4; j++) acc[i][j] = 0.f;

    for (int k0 = 0; k0 < DIN; k0 += 64) {
#pragma unroll
        for (int i = 0; i < 16; i++) {
            int e = tid + i * 256;
            int r = e >> 6, c = e & 63;
            Xs[c * 68 + r] = X[(size_t)(rowBase + r) * DIN + k0 + c];
            Ws[r * 64 + c] = d_Wt[(k0 + r) * DOUT + c];
        }
        __syncthreads();
#pragma unroll
        for (int kk = 0; kk < 64; kk++) {
            float4 a = *reinterpret_cast<const float4*>(&Xs[kk * 68 + ty * 4]);
            float4 b = *reinterpret_cast<const float4*>(&Ws[kk * 64 + tx * 4]);
            float av[4] = {a.x, a.y, a.z, a.w};
            float bv[4] = {b.x, b.y, b.z, b.w};
#pragma unroll
            for (int i = 0; i < 4; i++)
#pragma unroll
                for (int j = 0; j < 4; j++) acc[i][j] = fmaf(av[i], bv[j], acc[i][j]);
        }
        __syncthreads();
    }

#pragma unroll
    for (int i = 0; i < 4; i++)
#pragma unroll
        for (int j = 0; j < 4; j++) {
            float v = acc[i][j] + bias[tx * 4 + j];
            v = fmaxf(v, 0.f);
            d_P[blockIdx.y][(rowBase + ty * 4 + i) * DOUT + tx * 4 + j] = v;
        }
}

// ---------------------------------------------------------------------------
// 0.5 * ||row||^2, one warp per row
// ---------------------------------------------------------------------------
__global__ void k_sqnorm() {
    int wid = threadIdx.x >> 5, lane = threadIdx.x & 31;
    int grow = blockIdx.x * 8 + wid;
    int b = grow >> 11, r = grow & (NPTS - 1);
    float v0 = d_P[b][r * DOUT + lane];
    float v1 = d_P[b][r * DOUT + 32 + lane];
    float v = v0 * v0 + v1 * v1;
#pragma unroll
    for (int off = 16; off > 0; off >>= 1)
        v += __shfl_xor_sync(0xffffffffu, v, off);
    if (lane == 0) d_SQ[b][r] = 0.5f * v;
}

// ---------------------------------------------------------------------------
// cost: C[i][j] = 0.5||a_i||^2 + 0.5||b_j||^2 - a_i . b_j  (K=64)
// 64(i) x 128(j) tile, 4x8 per thread (3 LDS.128 per 32 FMA), K-chunks of 32.
// Thread's 8 cols = {tx*4..+3} and {64+tx*4..+3} (conflict-free LDS).
// XY matrices (z=3,4) also write the transpose via smem staging.
// ---------------------------------------------------------------------------
__global__ __launch_bounds__(256) void k_cost() {
    __shared__ __align__(16) char raw[33280];     // max(25600 gemm, 33280 sT)
    float (*sA)[68]  = reinterpret_cast<float (*)[68]>(raw);          // [32][68]
    float (*sB)[132] = reinterpret_cast<float (*)[132]>(raw + 8704);  // [32][132]
    const int z = blockIdx.z;
    const int ai = cAi[z], bi = cBi[z], ci = cCi[z], ti = cTi[z];
    const float* A = d_P[ai];
    const float* B = d_P[bi];
    const int i0 = blockIdx.y * 64, j0 = blockIdx.x * 128;
    const int tid = threadIdx.x;
    const int ty = tid >> 4, tx = tid & 15;

    float acc[4][8];
#pragma unroll
    for (int i = 0; i < 4; i++)
#pragma unroll
        for (int j = 0; j < 8; j++) acc[i][j] = 0.f;

    for (int k0 = 0; k0 < DOUT; k0 += 32) {
        // load A tile 64 rows x 32 k (conflict-free scatter: row varies in warp)
#pragma unroll
        for (int i = 0; i < 2; i++) {
            int e = tid + i * 256;            // 0..511
            int row = e & 63, kq = e >> 6;    // kq 0..7
            float4 v = *reinterpret_cast<const float4*>(
                A + (size_t)(i0 + row) * DOUT + k0 + kq * 4);
            sA[kq * 4 + 0][row] = v.x; sA[kq * 4 + 1][row] = v.y;
            sA[kq * 4 + 2][row] = v.z; sA[kq * 4 + 3][row] = v.w;
        }
        // load B tile 128 rows(cols of C) x 32 k
#pragma unroll
        for (int i = 0; i < 4; i++) {
            int e = tid + i * 256;            // 0..1023
            int row = e & 127, kq = e >> 7;   // kq 0..7
            float4 v = *reinterpret_cast<const float4*>(
                B + (size_t)(j0 + row) * DOUT + k0 + kq * 4);
            sB[kq * 4 + 0][row] = v.x; sB[kq * 4 + 1][row] = v.y;
            sB[kq * 4 + 2][row] = v.z; sB[kq * 4 + 3][row] = v.w;
        }
        __syncthreads();
#pragma unroll
        for (int kk = 0; kk < 32; kk++) {
            float4 a  = *reinterpret_cast<const float4*>(&sA[kk][ty * 4]);
            float4 b0 = *reinterpret_cast<const float4*>(&sB[kk][tx * 4]);
            float4 b1 = *reinterpret_cast<const float4*>(&sB[kk][64 + tx * 4]);
            float av[4] = {a.x, a.y, a.z, a.w};
            float bv[8] = {b0.x, b0.y, b0.z, b0.w, b1.x, b1.y, b1.z, b1.w};
#pragma unroll
            for (int i = 0; i < 4; i++)
#pragma unroll
                for (int j = 0; j < 8; j++)
                    acc[i][j] = fmaf(av[i], bv[j], acc[i][j]);
        }
        __syncthreads();
    }

    float sqa[4], sqb[8];
#pragma unroll
    for (int i = 0; i < 4; i++) sqa[i] = d_SQ[ai][i0 + ty * 4 + i];
#pragma unroll
    for (int j = 0; j < 8; j++) {
        int col = (j >> 2) * 64 + tx * 4 + (j & 3);
        sqb[j] = d_SQ[bi][j0 + col];
    }

    float val[4][8];
    float* Cm = d_C[ci];
#pragma unroll
    for (int i = 0; i < 4; i++) {
#pragma unroll
        for (int j = 0; j < 8; j++) val[i][j] = sqa[i] + sqb[j] - acc[i][j];
        float4 o0 = make_float4(val[i][0], val[i][1], val[i][2], val[i][3]);
        float4 o1 = make_float4(val[i][4], val[i][5], val[i][6], val[i][7]);
        float* dst = Cm + (size_t)(i0 + ty * 4 + i) * NPTS + j0;
        *reinterpret_cast<float4*>(dst + tx * 4) = o0;
        *reinterpret_cast<float4*>(dst + 64 + tx * 4) = o1;
    }

    if (ti >= 0) {
        // all threads are past the final __syncthreads(); smem is free
        float* sT = reinterpret_cast<float*>(raw);     // [128 cols][65]
#pragma unroll
        for (int i = 0; i < 4; i++)
#pragma unroll
            for (int j = 0; j < 8; j++) {
                int col = (j >> 2) * 64 + tx * 4 + (j & 3);
                sT[col * 65 + ty * 4 + i] = val[i][j];
            }
        __syncthreads();
        float* Ct = d_C[ti];
#pragma unroll
        for (int i = 0; i < 8; i++) {
            int e = tid + i * 256;          // 2048 float4 over 128x64
            int col = e >> 4, rq = e & 15;
            float4 w;
            w.x = sT[col * 65 + rq * 4 + 0];
            w.y = sT[col * 65 + rq * 4 + 1];
            w.z = sT[col * 65 + rq * 4 + 2];
            w.w = sT[col * 65 + rq * 4 + 3];
            *reinterpret_cast<float4*>(
                Ct + (size_t)(j0 + col) * NPTS + i0 + rq * 4) = w;
        }
    }
}

// ---------------------------------------------------------------------------
// zero ping-pong potential buffers
// ---------------------------------------------------------------------------
__global__ void k_init() {
    int e = blockIdx.x * blockDim.x + threadIdx.x;
    if (e < 2 * 7 * NPTS) (&d_pot[0][0][0])[e] = 0.f;
}

// ---------------------------------------------------------------------------
// One Sinkhorn scan step, all 7 passes row-mode (grid = 7*256, 8 rows/block,
// 1 row/warp, 16 chunks of 128 cols). [R11-proven shape]
//   mode 0: plain streaming (2 chunks of 1024, register-resident xv)
//   mode 1: process all chunks, init V[pass][row][chunk] = min_j∈c (C_ij-g_j)
//   mode 2: maintain V (exact processed / drift-decayed skipped), skip chunks
//           with ub < (argmax-chunk max) - SKIP_MARGIN
// f_i = eps*(ln N - ln2 * LSE2_j[(vin_j - C_ij)*log2e/eps])
// ---------------------------------------------------------------------------
__global__ __launch_bounds__(256) void k_step(int cur, float eps, int avg,
                                              int fin, int mode) {
    __shared__ __align__(16) float sg[NPTS];
    __shared__ float sdrift[NCHUNK];

    const int pp = blockIdx.x >> 8;                // 256 blocks per pass
    const int sub = blockIdx.x & 255;              // 8 rows each
    const int vinSlot = (pp < 3) ? pp : (((pp - 3) ^ 1) + 3);
    const float* __restrict__ vin  = d_pot[cur][vinSlot];
    const float* __restrict__ favg = d_pot[cur][pp];
    float* __restrict__ out = fin ? d_potF[pp] : d_pot[cur ^ 1][pp];
    const float* __restrict__ Cm = d_C[pp];
    const float pscale = LOG2E / eps;
    const float nscale = -pscale;
    const float c2u = eps * LN2;                   // log2-units -> C-units
    const int wid = threadIdx.x >> 5, lane = threadIdx.x & 31;

    // stage vin * (log2e/eps) into shared
    {
        const float4* vin4 = reinterpret_cast<const float4*>(vin);
        float4* sg4s = reinterpret_cast<float4*>(sg);
        for (int j = threadIdx.x; j < NPTS / 4; j += 256) {
            float4 v = vin4[j];
            v.x *= pscale; v.y *= pscale; v.z *= pscale; v.w *= pscale;
            sg4s[j] = v;
        }
    }

    // snapshot raw vin slice for next step's drift (exclusive 8-elem slice)
    if (mode >= 1 && threadIdx.x < 8)
        d_prev[cur][pp][sub * 8 + threadIdx.x] = vin[sub * 8 + threadIdx.x];

    // per-chunk drift vs previous step's vin (C units)
    if (mode == 2) {
        const float4* vin4 = reinterpret_cast<const float4*>(vin);
        const float4* prv4 = reinterpret_cast<const float4*>(d_prev[cur ^ 1][pp]);
        for (int cc = wid; cc < NCHUNK; cc += 8) {
            float4 v = vin4[cc * 32 + lane];
            float4 p = prv4[cc * 32 + lane];
            float d = fmaxf(fmaxf(v.x - p.x, v.y - p.y),
                            fmaxf(v.z - p.z, v.w - p.w));
#pragma unroll
            for (int off = 16; off > 0; off >>= 1)
                d = fmaxf(d, __shfl_xor_sync(0xffffffffu, d, off));
            if (lane == 0) sdrift[cc] = d;
        }
    }
    __syncthreads();

    const float4* sg4 = reinterpret_cast<const float4*>(sg);
    const int row = sub * 8 + wid;
    const float4* __restrict__ Crow4 =
        reinterpret_cast<const float4*>(Cm + (size_t)row * NPTS);

    float m, s;

    if (mode == 0) {
        // ---------------- plain streaming (proven fastest dense path) ------
        float4 xv[8];
        float m1 = -3.4e38f;
#pragma unroll
        for (int k = 0; k < 8; k++) {
            float4 c = Crow4[k * 32 + lane];
            float4 g = sg4[k * 32 + lane];
            float4 t;
            t.x = fmaf(c.x, nscale, g.x);
            t.y = fmaf(c.y, nscale, g.y);
            t.z = fmaf(c.z, nscale, g.z);
            t.w = fmaf(c.w, nscale, g.w);
            xv[k] = t;
            m1 = fmaxf(m1, fmaxf(fmaxf(t.x, t.y), fmaxf(t.z, t.w)));
        }
        float s1 = 0.f;
#pragma unroll
        for (int k = 0; k < 8; k++)
            s1 += ex2f(xv[k].x - m1) + ex2f(xv[k].y - m1)
                + ex2f(xv[k].z - m1) + ex2f(xv[k].w - m1);

        float m2 = -3.4e38f;
#pragma unroll
        for (int k = 0; k < 8; k++) {
            float4 c = Crow4[256 + k * 32 + lane];
            float4 g = sg4[256 + k * 32 + lane];
            float4 t;
            t.x = fmaf(c.x, nscale, g.x);
            t.y = fmaf(c.y, nscale, g.y);
            t.z = fmaf(c.z, nscale, g.z);
            t.w = fmaf(c.w, nscale, g.w);
            xv[k] = t;
            m2 = fmaxf(m2, fmaxf(fmaxf(t.x, t.y), fmaxf(t.z, t.w)));
        }
        float s2 = 0.f;
#pragma unroll
        for (int k = 0; k < 8; k++)
            s2 += ex2f(xv[k].x - m2) + ex2f(xv[k].y - m2)
                + ex2f(xv[k].z - m2) + ex2f(xv[k].w - m2);

        m = fmaxf(m1, m2);
        s = s1 * ex2f(m1 - m) + s2 * ex2f(m2 - m);
    } else {
        // ---------------- V-maintained modes: 16 x 128-col chunks ---------
        float Vc = 0.f;
        float ub = -3.4e38f;
        if (mode == 2 && lane < NCHUNK) {
            Vc = d_V[pp][row][lane] - sdrift[lane];
            ub = -Vc * pscale;
        }

        int c1 = 0;
        if (mode == 2) {
            float av = ub; int bi = lane;
#pragma unroll
            for (int off = 16; off > 0; off >>= 1) {
                float vo = __shfl_xor_sync(0xffffffffu, av, off);
                int   io = __shfl_xor_sync(0xffffffffu, bi, off);
                if (vo > av || (vo == av && io < bi)) { av = vo; bi = io; }
            }
            c1 = bi;
        }

        float mglob;
        {
            float4 cc4 = Crow4[c1 * 32 + lane];
            float4 gg = sg4[c1 * 32 + lane];
            float4 t;
            t.x = fmaf(cc4.x, nscale, gg.x);
            t.y = fmaf(cc4.y, nscale, gg.y);
            t.z = fmaf(cc4.z, nscale, gg.z);
            t.w = fmaf(cc4.w, nscale, gg.w);
            float mc = fmaxf(fmaxf(t.x, t.y), fmaxf(t.z, t.w));
            float mw = mc;
#pragma unroll
            for (int off = 16; off > 0; off >>= 1)
                mw = fmaxf(mw, __shfl_xor_sync(0xffffffffu, mw, off));
            mglob = mw;
            m = mc;
            s = ex2f(t.x - m) + ex2f(t.y - m) + ex2f(t.z - m) + ex2f(t.w - m);
            if (lane == c1) Vc = -mw * c2u;
        }

#pragma unroll 1
        for (int c = 0; c < NCHUNK; ++c) {
            if (c == c1) continue;
            if (mode == 2) {
                float ubc = __shfl_sync(0xffffffffu, ub, c);
                if (ubc < mglob - SKIP_MARGIN) continue;
            }
            float4 cc4 = Crow4[c * 32 + lane];
            float4 gg = sg4[c * 32 + lane];
            float4 t;
            t.x = fmaf(cc4.x, nscale, gg.x);
            t.y = fmaf(cc4.y, nscale, gg.y);
            t.z = fmaf(cc4.z, nscale, gg.z);
            t.w = fmaf(cc4.w, nscale, gg.w);
            float mc = fmaxf(fmaxf(t.x, t.y), fmaxf(t.z, t.w));
            float mw = mc;
#pragma unroll
            for (int off = 16; off > 0; off >>= 1)
                mw = fmaxf(mw, __shfl_xor_sync(0xffffffffu, mw, off));
            if (lane == c) Vc = -mw * c2u;
            float mn = fmaxf(m, mw);
            s = s * ex2f(m - mn)
              + ex2f(t.x - mn) + ex2f(t.y - mn)
              + ex2f(t.z - mn) + ex2f(t.w - mn);
            m = mn;
        }

        if (lane < NCHUNK)
            d_V[pp][row][lane] = Vc;
    }

    // warp LSE combine
#pragma unroll
    for (int off = 16; off > 0; off >>= 1) {
        float mo = __shfl_xor_sync(0xffffffffu, m, off);
        float so = __shfl_xor_sync(0xffffffffu, s, off);
        float mn = fmaxf(m, mo);
        s = s * ex2f(m - mn) + so * ex2f(mo - mn);
        m = mn;
    }

    if (lane == 0) {
        float ft = eps * (LN_N - (m + lg2f(s)) * LN2);
        out[row] = avg ? 0.5f * (favg[row] + ft) : ft;
    }
}

// ---------------------------------------------------------------------------
// dist1 = <a, f_xy1 - f_xx> + <b, g_xy1 - g_y1y1>, dist2 analogous.
// out = sigmoid(10 * (dist2 - dist1))
// ---------------------------------------------------------------------------
__global__ void k_reduce(float* out) {
    __shared__ float s1h[256], s2h[256];
    int t = threadIdx.x;
    float a1 = 0.f, a2 = 0.f;
    for (int i = t; i < NPTS; i += 256) {
        float fxx = d_potF[0][i];
        a1 += (d_potF[3][i] - fxx) + (d_potF[4][i] - d_potF[1][i]);
        a2 += (d_potF[5][i] - fxx) + (d_potF[6][i] - d_potF[2][i]);
    }
    s1h[t] = a1;
    s2h[t] = a2;
    __syncthreads();
    for (int off = 128; off > 0; off >>= 1) {
        if (t < off) { s1h[t] += s1h[t + off]; s2h[t] += s2h[t + off]; }
        __syncthreads();
    }
    if (t == 0) {
        const float inv = 1.0f / (float)NPTS;
        float dist1 = s1h[0] * inv;
        float dist2 = s2h[0] * inv;
        float z = 10.0f * (dist2 - dist1);
        out[0] = 1.0f / (1.0f + expf(-z));
    }
}

// ---------------------------------------------------------------------------
// Launcher (graph-capturable: kernel launches only)
// ---------------------------------------------------------------------------
extern "C" void kernel_launch(void* const* d_in, const int* in_sizes, int n_in,
                              void* d_out, int out_size) {
    (void)in_sizes; (void)n_in; (void)out_size;
    const float* dX = (const float*)d_in[0];
    const float* s1 = (const float*)d_in[1];
    const float* s2 = (const float*)d_in[2];
    const float* W  = (const float*)d_in[3];
    const float* bb = (const float*)d_in[4];
    float* out = (float*)d_out;

    k_transposeW<<<(DIN * DOUT + 255) / 256, 256>>>(W);
    k_predict<<<dim3(NPTS / 64, 3), 256>>>(dX, s1, s2, bb);
    k_sqnorm<<<3 * NPTS / 8, 256>>>();
    k_cost<<<dim3(16, 32, 5), 256>>>();
    k_init<<<(2 * 7 * NPTS + 255) / 256, 256>>>();

    // epsilon schedule (geomloss-style), computed in double, cast to float
    const double eps0 = 32.0;
    const double epsf = pow(0.05, 2.0);
    const double ratio = pow(0.9, 2.0);
    int n = (int)ceil(log(epsf / eps0) / log(ratio));   // 45
    float sched[64];
    int cnt = 0;
    for (int k = 0; k <= n; k++) {
        double v = eps0 * pow(ratio, (double)k);
        if (v < epsf) v = epsf;
        sched[cnt++] = (float)v;
    }
    sched[cnt++] = (float)epsf;                          // cnt = 47

    for (int k = 0; k < cnt; k++) {
        int mode = (k < SKIP_START) ? 0 : (k == SKIP_START ? 1 : 2);
        k_step<<<7 * 256, 256>>>(k & 1, sched[k], 1, 0, mode);
    }

    // final differentiable update at eps_f (no averaging, write final arrays)
    k_step<<<7 * 256, 256>>>(cnt & 1, (float)epsf, 0, 1, 2);

    k_reduce<<<1, 256>>>(out);
}

// round 15
// speedup vs baseline: 1.0651x; 1.0651x over previous
#include <cuda_runtime.h>
#include <math.h>

#define NPTS 2048
#define DIN  768
#define DOUT 64
#define NMAT 7
#define NCHUNK 16                      // 128-column chunks per row
#define LN_N   7.624618986159398f      // ln(2048)
#define LOG2E  1.4426950408889634f
#define LN2    0.6931471805599453f
#define SKIP_START 20                  // first step with V maintenance (R11 value)

// ---------------------------------------------------------------------------
// Device scratch (static globals — no allocation in kernel_launch)
// ---------------------------------------------------------------------------
__device__ __align__(16) float d_Wt[DIN * DOUT];             // W^T: [768][64]
__device__ __align__(16) float d_P[3][NPTS * DOUT];          // pd, p1, p2
__device__ __align__(16) float d_SQ[3][NPTS];                // 0.5*||row||^2
__device__ __align__(16) float d_C[NMAT][(size_t)NPTS * NPTS];
// 0:Cxx 1:C11 2:C22 3:Cxy1 4:Cyx1 5:Cxy2 6:Cyx2
__device__ __align__(16) float d_pot[2][7][NPTS];            // ping-pong potentials
// slots: 0:f_xx 1:f_11 2:f_22 3:f_xy1 4:g_xy1 5:f_xy2 6:g_xy2
__device__ __align__(16) float d_potF[7][NPTS];              // final potentials
__device__ __align__(16) float d_V[NMAT][NPTS][NCHUNK];      // min_j∈c (C_ij - g_j)
__device__ __align__(16) float d_prev[2][NMAT][NPTS];        // vin snapshots (2-buf)

__constant__ int cAi[5] = {0, 1, 2, 0, 0};
__constant__ int cBi[5] = {0, 1, 2, 1, 2};
__constant__ int cCi[5] = {0, 1, 2, 3, 5};
__constant__ int cTi[5] = {-1, -1, -1, 4, 6};

__device__ __forceinline__ float ex2f(float x) {
    float r; asm("ex2.approx.ftz.f32 %0, %1;" : "=f"(r) : "f"(x)); return r;
}
__device__ __forceinline__ float lg2f(float x) {
    float r; asm("lg2.approx.f32 %0, %1;" : "=f"(r) : "f"(x)); return r;
}

// ---------------------------------------------------------------------------
// W transpose:  Wt[j][k] = W[k][j]
// ---------------------------------------------------------------------------
__global__ void k_transposeW(const float* __restrict__ W) {
    int e = blockIdx.x * blockDim.x + threadIdx.x;
    if (e < DIN * DOUT) {
        int j = e / DOUT, k = e % DOUT;
        d_Wt[e] = W[k * DIN + j];
    }
}

// ---------------------------------------------------------------------------
// predict: P = relu(X @ W^T + b). 64x64 tile / 256 threads.
// ---------------------------------------------------------------------------
__global__ __launch_bounds__(256) void k_predict(const float* __restrict__ X0,
                                                 const float* __restrict__ X1,
                                                 const float* __restrict__ X2,
                                                 const float* __restrict__ bias) {
    __shared__ __align__(16) float Xs[64 * 68];   // [kk][row]
    __shared__ __align__(16) float Ws[64 * 64];   // [kk][col]
    const float* X = (blockIdx.y == 0) ? X0 : (blockIdx.y == 1) ? X1 : X2;
    int rowBase = blockIdx.x * 64;
    int tid = threadIdx.x;
    int ty = tid >> 4, tx = tid & 15;

    float acc[4][4];
#pragma unroll
    for (int i = 0; i < 4; i++)
#pragma unroll
        for (int j = 0; j < 4; j++) acc[i][j] = 0.f;

    for (int k0 = 0; k0 < DIN; k0 += 64) {
#pragma unroll
        for (int i = 0; i < 16; i++) {
            int e = tid + i * 256;
            int r = e >> 6, c = e & 63;
            Xs[c * 68 + r] = X[(size_t)(rowBase + r) * DIN + k0 + c];
            Ws[r * 64 + c] = d_Wt[(k0 + r) * DOUT + c];
        }
        __syncthreads();
#pragma unroll
        for (int kk = 0; kk < 64; kk++) {
            float4 a = *reinterpret_cast<const float4*>(&Xs[kk * 68 + ty * 4]);
            float4 b = *reinterpret_cast<const float4*>(&Ws[kk * 64 + tx * 4]);
            float av[4] = {a.x, a.y, a.z, a.w};
            float bv[4] = {b.x, b.y, b.z, b.w};
#pragma unroll
            for (int i = 0; i < 4; i++)
#pragma unroll
                for (int j = 0; j < 4; j++) acc[i][j] = fmaf(av[i], bv[j], acc[i][j]);
        }
        __syncthreads();
    }

#pragma unroll
    for (int i = 0; i < 4; i++)
#pragma unroll
        for (int j = 0; j < 4; j++) {
            float v = acc[i][j] + bias[tx * 4 + j];
            v = fmaxf(v, 0.f);
            d_P[blockIdx.y][(rowBase + ty * 4 + i) * DOUT + tx * 4 + j] = v;
        }
}

// ---------------------------------------------------------------------------
// 0.5 * ||row||^2, one warp per row
// ---------------------------------------------------------------------------
__global__ void k_sqnorm() {
    int wid = threadIdx.x >> 5, lane = threadIdx.x & 31;
    int grow = blockIdx.x * 8 + wid;
    int b = grow >> 11, r = grow & (NPTS - 1);
    float v0 = d_P[b][r * DOUT + lane];
    float v1 = d_P[b][r * DOUT + 32 + lane];
    float v = v0 * v0 + v1 * v1;
#pragma unroll
    for (int off = 16; off > 0; off >>= 1)
        v += __shfl_xor_sync(0xffffffffu, v, off);
    if (lane == 0) d_SQ[b][r] = 0.5f * v;
}

// ---------------------------------------------------------------------------
// cost: C[i][j] = 0.5||a_i||^2 + 0.5||b_j||^2 - a_i . b_j  (K=64)
// 64x64 tile, 4x4/thread; 5 products via blockIdx.z, XY also write transpose.
// ---------------------------------------------------------------------------
__global__ __launch_bounds__(256) void k_cost() {
    __shared__ __align__(16) float sA[64 * 68];   // [kk][row]
    __shared__ __align__(16) float sB[64 * 68];   // [kk][col]
    const int z = blockIdx.z;
    const int ai = cAi[z], bi = cBi[z], ci = cCi[z], ti = cTi[z];
    const float* A = d_P[ai];
    const float* B = d_P[bi];
    int i0 = blockIdx.y * 64, j0 = blockIdx.x * 64;
    int tid = threadIdx.x, ty = tid >> 4, tx = tid & 15;

#pragma unroll
    for (int i = 0; i < 16; i++) {
        int e = tid + i * 256;
        int r = e >> 6, c = e & 63;
        sA[c * 68 + r] = A[(i0 + r) * DOUT + c];
        sB[c * 68 + r] = B[(j0 + r) * DOUT + c];
    }
    __syncthreads();

    float acc[4][4];
#pragma unroll
    for (int i = 0; i < 4; i++)
#pragma unroll
        for (int j = 0; j < 4; j++) acc[i][j] = 0.f;

#pragma unroll
    for (int kk = 0; kk < 64; kk++) {
        float4 a = *reinterpret_cast<const float4*>(&sA[kk * 68 + ty * 4]);
        float4 b = *reinterpret_cast<const float4*>(&sB[kk * 68 + tx * 4]);
        float av[4] = {a.x, a.y, a.z, a.w};
        float bv[4] = {b.x, b.y, b.z, b.w};
#pragma unroll
        for (int i = 0; i < 4; i++)
#pragma unroll
            for (int j = 0; j < 4; j++) acc[i][j] = fmaf(av[i], bv[j], acc[i][j]);
    }

    float sqa[4], sqb[4];
#pragma unroll
    for (int i = 0; i < 4; i++) sqa[i] = d_SQ[ai][i0 + ty * 4 + i];
#pragma unroll
    for (int j = 0; j < 4; j++) sqb[j] = d_SQ[bi][j0 + tx * 4 + j];

    float val[4][4];
    float* Cm = d_C[ci];
#pragma unroll
    for (int i = 0; i < 4; i++)
#pragma unroll
        for (int j = 0; j < 4; j++) {
            val[i][j] = sqa[i] + sqb[j] - acc[i][j];
            Cm[(size_t)(i0 + ty * 4 + i) * NPTS + j0 + tx * 4 + j] = val[i][j];
        }

    if (ti >= 0) {
        __syncthreads();            // done reading sA
#pragma unroll
        for (int i = 0; i < 4; i++)
#pragma unroll
            for (int j = 0; j < 4; j++)
                sA[(tx * 4 + j) * 65 + ty * 4 + i] = val[i][j];
        __syncthreads();
        float* Ct = d_C[ti];
#pragma unroll
        for (int i = 0; i < 16; i++) {
            int e = tid + i * 256;
            int r = e >> 6, c = e & 63;
            Ct[(size_t)(j0 + r) * NPTS + i0 + c] = sA[r * 65 + c];
        }
    }
}

// ---------------------------------------------------------------------------
// zero ping-pong potential buffers
// ---------------------------------------------------------------------------
__global__ void k_init() {
    int e = blockIdx.x * blockDim.x + threadIdx.x;
    if (e < 2 * 7 * NPTS) (&d_pot[0][0][0])[e] = 0.f;
}

// ---------------------------------------------------------------------------
// One Sinkhorn scan step, all 7 passes row-mode (grid = 7*256, 8 rows/block,
// 1 row/warp, 16 chunks of 128 cols). [R11-proven shape, byte-faithful]
//   mode 0: plain streaming (2 chunks of 1024, register-resident xv)
//   mode 1: process all chunks, init V[pass][row][chunk] = min_j∈c (C_ij-g_j)
//   mode 2: maintain V (exact processed / drift-decayed skipped), skip chunks
//           with ub < (argmax-chunk max) - margin. margin is eps-adaptive:
//           margin = clamp(25 + log2(eps), 18, 30) so skipped relative mass
//           keeps eps*ln(1+rho) <= 1e-4 uniformly across the schedule.
// f_i = eps*(ln N - ln2 * LSE2_j[(vin_j - C_ij)*log2e/eps])
// ---------------------------------------------------------------------------
__global__ __launch_bounds__(256) void k_step(int cur, float eps, int avg,
                                              int fin, int mode, float margin) {
    __shared__ __align__(16) float sg[NPTS];
    __shared__ float sdrift[NCHUNK];

    const int pp = blockIdx.x >> 8;                // 256 blocks per pass
    const int sub = blockIdx.x & 255;              // 8 rows each
    const int vinSlot = (pp < 3) ? pp : (((pp - 3) ^ 1) + 3);
    const float* __restrict__ vin  = d_pot[cur][vinSlot];
    const float* __restrict__ favg = d_pot[cur][pp];
    float* __restrict__ out = fin ? d_potF[pp] : d_pot[cur ^ 1][pp];
    const float* __restrict__ Cm = d_C[pp];
    const float pscale = LOG2E / eps;
    const float nscale = -pscale;
    const float c2u = eps * LN2;                   // log2-units -> C-units
    const int wid = threadIdx.x >> 5, lane = threadIdx.x & 31;

    // stage vin * (log2e/eps) into shared
    {
        const float4* vin4 = reinterpret_cast<const float4*>(vin);
        float4* sg4s = reinterpret_cast<float4*>(sg);
        for (int j = threadIdx.x; j < NPTS / 4; j += 256) {
            float4 v = vin4[j];
            v.x *= pscale; v.y *= pscale; v.z *= pscale; v.w *= pscale;
            sg4s[j] = v;
        }
    }

    // snapshot raw vin slice for next step's drift (exclusive 8-elem slice)
    if (mode >= 1 && threadIdx.x < 8)
        d_prev[cur][pp][sub * 8 + threadIdx.x] = vin[sub * 8 + threadIdx.x];

    // per-chunk drift vs previous step's vin (C units)
    if (mode == 2) {
        const float4* vin4 = reinterpret_cast<const float4*>(vin);
        const float4* prv4 = reinterpret_cast<const float4*>(d_prev[cur ^ 1][pp]);
        for (int cc = wid; cc < NCHUNK; cc += 8) {
            float4 v = vin4[cc * 32 + lane];
            float4 p = prv4[cc * 32 + lane];
            float d = fmaxf(fmaxf(v.x - p.x, v.y - p.y),
                            fmaxf(v.z - p.z, v.w - p.w));
#pragma unroll
            for (int off = 16; off > 0; off >>= 1)
                d = fmaxf(d, __shfl_xor_sync(0xffffffffu, d, off));
            if (lane == 0) sdrift[cc] = d;
        }
    }
    __syncthreads();

    const float4* sg4 = reinterpret_cast<const float4*>(sg);
    const int row = sub * 8 + wid;
    const float4* __restrict__ Crow4 =
        reinterpret_cast<const float4*>(Cm + (size_t)row * NPTS);

    float m, s;

    if (mode == 0) {
        // ---------------- plain streaming (proven fastest dense path) ------
        float4 xv[8];
        float m1 = -3.4e38f;
#pragma unroll
        for (int k = 0; k < 8; k++) {
            float4 c = Crow4[k * 32 + lane];
            float4 g = sg4[k * 32 + lane];
            float4 t;
            t.x = fmaf(c.x, nscale, g.x);
            t.y = fmaf(c.y, nscale, g.y);
            t.z = fmaf(c.z, nscale, g.z);
            t.w = fmaf(c.w, nscale, g.w);
            xv[k] = t;
            m1 = fmaxf(m1, fmaxf(fmaxf(t.x, t.y), fmaxf(t.z, t.w)));
        }
        float s1 = 0.f;
#pragma unroll
        for (int k = 0; k < 8; k++)
            s1 += ex2f(xv[k].x - m1) + ex2f(xv[k].y - m1)
                + ex2f(xv[k].z - m1) + ex2f(xv[k].w - m1);

        float m2 = -3.4e38f;
#pragma unroll
        for (int k = 0; k < 8; k++) {
            float4 c = Crow4[256 + k * 32 + lane];
            float4 g = sg4[256 + k * 32 + lane];
            float4 t;
            t.x = fmaf(c.x, nscale, g.x);
            t.y = fmaf(c.y, nscale, g.y);
            t.z = fmaf(c.z, nscale, g.z);
            t.w = fmaf(c.w, nscale, g.w);
            xv[k] = t;
            m2 = fmaxf(m2, fmaxf(fmaxf(t.x, t.y), fmaxf(t.z, t.w)));
        }
        float s2 = 0.f;
#pragma unroll
        for (int k = 0; k < 8; k++)
            s2 += ex2f(xv[k].x - m2) + ex2f(xv[k].y - m2)
                + ex2f(xv[k].z - m2) + ex2f(xv[k].w - m2);

        m = fmaxf(m1, m2);
        s = s1 * ex2f(m1 - m) + s2 * ex2f(m2 - m);
    } else {
        // ---------------- V-maintained modes: 16 x 128-col chunks ---------
        float Vc = 0.f;
        float ub = -3.4e38f;
        if (mode == 2 && lane < NCHUNK) {
            Vc = d_V[pp][row][lane] - sdrift[lane];
            ub = -Vc * pscale;
        }

        int c1 = 0;
        if (mode == 2) {
            float av = ub; int bi = lane;
#pragma unroll
            for (int off = 16; off > 0; off >>= 1) {
                float vo = __shfl_xor_sync(0xffffffffu, av, off);
                int   io = __shfl_xor_sync(0xffffffffu, bi, off);
                if (vo > av || (vo == av && io < bi)) { av = vo; bi = io; }
            }
            c1 = bi;
        }

        float mglob;
        {
            float4 cc4 = Crow4[c1 * 32 + lane];
            float4 gg = sg4[c1 * 32 + lane];
            float4 t;
            t.x = fmaf(cc4.x, nscale, gg.x);
            t.y = fmaf(cc4.y, nscale, gg.y);
            t.z = fmaf(cc4.z, nscale, gg.z);
            t.w = fmaf(cc4.w, nscale, gg.w);
            float mc = fmaxf(fmaxf(t.x, t.y), fmaxf(t.z, t.w));
            float mw = mc;
#pragma unroll
            for (int off = 16; off > 0; off >>= 1)
                mw = fmaxf(mw, __shfl_xor_sync(0xffffffffu, mw, off));
            mglob = mw;
            m = mc;
            s = ex2f(t.x - m) + ex2f(t.y - m) + ex2f(t.z - m) + ex2f(t.w - m);
            if (lane == c1) Vc = -mw * c2u;
        }

#pragma unroll 1
        for (int c = 0; c < NCHUNK; ++c) {
            if (c == c1) continue;
            if (mode == 2) {
                float ubc = __shfl_sync(0xffffffffu, ub, c);
                if (ubc < mglob - margin) continue;
            }
            float4 cc4 = Crow4[c * 32 + lane];
            float4 gg = sg4[c * 32 + lane];
            float4 t;
            t.x = fmaf(cc4.x, nscale, gg.x);
            t.y = fmaf(cc4.y, nscale, gg.y);
            t.z = fmaf(cc4.z, nscale, gg.z);
            t.w = fmaf(cc4.w, nscale, gg.w);
            float mc = fmaxf(fmaxf(t.x, t.y), fmaxf(t.z, t.w));
            float mw = mc;
#pragma unroll
            for (int off = 16; off > 0; off >>= 1)
                mw = fmaxf(mw, __shfl_xor_sync(0xffffffffu, mw, off));
            if (lane == c) Vc = -mw * c2u;
            float mn = fmaxf(m, mw);
            s = s * ex2f(m - mn)
              + ex2f(t.x - mn) + ex2f(t.y - mn)
              + ex2f(t.z - mn) + ex2f(t.w - mn);
            m = mn;
        }

        if (lane < NCHUNK)
            d_V[pp][row][lane] = Vc;
    }

    // warp LSE combine
#pragma unroll
    for (int off = 16; off > 0; off >>= 1) {
        float mo = __shfl_xor_sync(0xffffffffu, m, off);
        float so = __shfl_xor_sync(0xffffffffu, s, off);
        float mn = fmaxf(m, mo);
        s = s * ex2f(m - mn) + so * ex2f(mo - mn);
        m = mn;
    }

    if (lane == 0) {
        float ft = eps * (LN_N - (m + lg2f(s)) * LN2);
        out[row] = avg ? 0.5f * (favg[row] + ft) : ft;
    }
}

// ---------------------------------------------------------------------------
// dist1 = <a, f_xy1 - f_xx> + <b, g_xy1 - g_y1y1>, dist2 analogous.
// out = sigmoid(10 * (dist2 - dist1))
// ---------------------------------------------------------------------------
__global__ void k_reduce(float* out) {
    __shared__ float s1h[256], s2h[256];
    int t = threadIdx.x;
    float a1 = 0.f, a2 = 0.f;
    for (int i = t; i < NPTS; i += 256) {
        float fxx = d_potF[0][i];
        a1 += (d_potF[3][i] - fxx) + (d_potF[4][i] - d_potF[1][i]);
        a2 += (d_potF[5][i] - fxx) + (d_potF[6][i] - d_potF[2][i]);
    }
    s1h[t] = a1;
    s2h[t] = a2;
    __syncthreads();
    for (int off = 128; off > 0; off >>= 1) {
        if (t < off) { s1h[t] += s1h[t + off]; s2h[t] += s2h[t + off]; }
        __syncthreads();
    }
    if (t == 0) {
        const float inv = 1.0f / (float)NPTS;
        float dist1 = s1h[0] * inv;
        float dist2 = s2h[0] * inv;
        float z = 10.0f * (dist2 - dist1);
        out[0] = 1.0f / (1.0f + expf(-z));
    }
}

// ---------------------------------------------------------------------------
// Launcher (graph-capturable: kernel launches only)
// ---------------------------------------------------------------------------
extern "C" void kernel_launch(void* const* d_in, const int* in_sizes, int n_in,
                              void* d_out, int out_size) {
    (void)in_sizes; (void)n_in; (void)out_size;
    const float* dX = (const float*)d_in[0];
    const float* s1 = (const float*)d_in[1];
    const float* s2 = (const float*)d_in[2];
    const float* W  = (const float*)d_in[3];
    const float* bb = (const float*)d_in[4];
    float* out = (float*)d_out;

    k_transposeW<<<(DIN * DOUT + 255) / 256, 256>>>(W);
    k_predict<<<dim3(NPTS / 64, 3), 256>>>(dX, s1, s2, bb);
    k_sqnorm<<<3 * NPTS / 8, 256>>>();
    k_cost<<<dim3(32, 32, 5), 256>>>();
    k_init<<<(2 * 7 * NPTS + 255) / 256, 256>>>();

    // epsilon schedule (geomloss-style), computed in double, cast to float
    const double eps0 = 32.0;
    const double epsf = pow(0.05, 2.0);
    const double ratio = pow(0.9, 2.0);
    int n = (int)ceil(log(epsf / eps0) / log(ratio));   // 45
    float sched[64];
    int cnt = 0;
    for (int k = 0; k <= n; k++) {
        double v = eps0 * pow(ratio, (double)k);
        if (v < epsf) v = epsf;
        sched[cnt++] = (float)v;
    }
    sched[cnt++] = (float)epsf;                          // cnt = 47

    for (int k = 0; k < cnt; k++) {
        int mode = (k < SKIP_START) ? 0 : (k == SKIP_START ? 1 : 2);
        double mg = 25.0 + log2((double)sched[k]);
        float margin = (float)(mg < 18.0 ? 18.0 : (mg > 30.0 ? 30.0 : mg));
        k_step<<<7 * 256, 256>>>(k & 1, sched[k], 1, 0, mode, margin);
    }

    // final differentiable update at eps_f (no averaging, write final arrays)
    {
        double mg = 25.0 + log2(epsf);
        float margin = (float)(mg < 18.0 ? 18.0 : (mg > 30.0 ? 30.0 : mg));
        k_step<<<7 * 256, 256>>>(cnt & 1, (float)epsf, 0, 1, 2, margin);
    }

    k_reduce<<<1, 256>>>(out);
}

// round 16
// speedup vs baseline: 1.3890x; 1.3041x over previous
#include <cuda_runtime.h>
#include <math.h>

#define NPTS 2048
#define DIN  768
#define DOUT 64
#define NMAT 5
#define NCHUNK 16                      // 128-column chunks per row
#define LN_N   7.624618986159398f      // ln(2048)
#define LOG2E  1.4426950408889634f
#define LN2    0.6931471805599453f
#define SKIP_MARGIN 30.0f              // R11-proven
#define SKIP_START 20                  // R11-proven

#define COLBLKS 128                    // 2 mats * 16 chunks * 4 slabs
#define ROWBLKS (5 * 256)              // 5 row passes, 8 rows/block
#define GRIDX   (COLBLKS + ROWBLKS)    // 1408

// ---------------------------------------------------------------------------
// Device scratch (static globals — no allocation in kernel_launch)
// ---------------------------------------------------------------------------
__device__ __align__(16) float d_Wt[DIN * DOUT];             // W^T: [768][64]
__device__ __align__(16) float d_P[3][NPTS * DOUT];          // pd, p1, p2
__device__ __align__(16) float d_SQ[3][NPTS];                // 0.5*||row||^2
__device__ __align__(16) float d_C[NMAT][(size_t)NPTS * NPTS];
// 0:Cxx 1:C11 2:C22 3:Cxy1 4:Cxy2   (80 MB — fits L2, stays resident)
__device__ __align__(16) float d_pot[2][7][NPTS];            // ping-pong potentials
// slots: 0:f_xx 1:f_11 2:f_22 3:f_xy1 4:g_xy1 5:f_xy2 6:g_xy2
__device__ __align__(16) float d_potF[7][NPTS];              // final potentials
__device__ __align__(16) float d_V[5][NPTS][NCHUNK];         // row-pass chunk bounds
__device__ __align__(16) float d_prev[2][5][NPTS];           // vin snapshots (2-buf)
// column-pass slab partials: [mat(2)][chunk(16)][slab(4)][col(128)]
__device__ __align__(16) float d_pm[2][16][4][128];
__device__ __align__(16) float d_ps[2][16][4][128];
__device__ unsigned g_cnt[2][16];                            // last-block counters

__constant__ int cAi[5] = {0, 1, 2, 0, 0};
__constant__ int cBi[5] = {0, 1, 2, 1, 2};
// row passes 0..4 read d_C[pass]; vin/out potential slots:
__constant__ int cVinRow[5] = {0, 1, 2, 4, 6};
__constant__ int cOutRow[5] = {0, 1, 2, 3, 5};

__device__ __forceinline__ float ex2f(float x) {
    float r; asm("ex2.approx.ftz.f32 %0, %1;" : "=f"(r) : "f"(x)); return r;
}
__device__ __forceinline__ float lg2f(float x) {
    float r; asm("lg2.approx.f32 %0, %1;" : "=f"(r) : "f"(x)); return r;
}

// ---------------------------------------------------------------------------
// W transpose:  Wt[j][k] = W[k][j]
// ---------------------------------------------------------------------------
__global__ void k_transposeW(const float* __restrict__ W) {
    int e = blockIdx.x * blockDim.x + threadIdx.x;
    if (e < DIN * DOUT) {
        int j = e / DOUT, k = e % DOUT;
        d_Wt[e] = W[k * DIN + j];
    }
}

// ---------------------------------------------------------------------------
// predict: P = relu(X @ W^T + b). 64x64 tile / 256 threads.
// ---------------------------------------------------------------------------
__global__ __launch_bounds__(256) void k_predict(const float* __restrict__ X0,
                                                 const float* __restrict__ X1,
                                                 const float* __restrict__ X2,
                                                 const float* __restrict__ bias) {
    __shared__ __align__(16) float Xs[64 * 68];   // [kk][row]
    __shared__ __align__(16) float Ws[64 * 64];   // [kk][col]
    const float* X = (blockIdx.y == 0) ? X0 : (blockIdx.y == 1) ? X1 : X2;
    int rowBase = blockIdx.x * 64;
    int tid = threadIdx.x;
    int ty = tid >> 4, tx = tid & 15;

    float acc[4][4];
#pragma unroll
    for (int i = 0; i < 4; i++)
#pragma unroll
        for (int j = 0; j < 4; j++) acc[i][j] = 0.f;

    for (int k0 = 0; k0 < DIN; k0 += 64) {
#pragma unroll
        for (int i = 0; i < 16; i++) {
            int e = tid + i * 256;
            int r = e >> 6, c = e & 63;
            Xs[c * 68 + r] = X[(size_t)(rowBase + r) * DIN + k0 + c];
            Ws[r * 64 + c] = d_Wt[(k0 + r) * DOUT + c];
        }
        __syncthreads();
#pragma unroll
        for (int kk = 0; kk < 64; kk++) {
            float4 a = *reinterpret_cast<const float4*>(&Xs[kk * 68 + ty * 4]);
            float4 b = *reinterpret_cast<const float4*>(&Ws[kk * 64 + tx * 4]);
            float av[4] = {a.x, a.y, a.z, a.w};
            float bv[4] = {b.x, b.y, b.z, b.w};
#pragma unroll
            for (int i = 0; i < 4; i++)
#pragma unroll
                for (int j = 0; j < 4; j++) acc[i][j] = fmaf(av[i], bv[j], acc[i][j]);
        }
        __syncthreads();
    }

#pragma unroll
    for (int i = 0; i < 4; i++)
#pragma unroll
        for (int j = 0; j < 4; j++) {
            float v = acc[i][j] + bias[tx * 4 + j];
            v = fmaxf(v, 0.f);
            d_P[blockIdx.y][(rowBase + ty * 4 + i) * DOUT + tx * 4 + j] = v;
        }
}

// ---------------------------------------------------------------------------
// 0.5 * ||row||^2, one warp per row
// ---------------------------------------------------------------------------
__global__ void k_sqnorm() {
    int wid = threadIdx.x >> 5, lane = threadIdx.x & 31;
    int grow = blockIdx.x * 8 + wid;
    int b = grow >> 11, r = grow & (NPTS - 1);
    float v0 = d_P[b][r * DOUT + lane];
    float v1 = d_P[b][r * DOUT + 32 + lane];
    float v = v0 * v0 + v1 * v1;
#pragma unroll
    for (int off = 16; off > 0; off >>= 1)
        v += __shfl_xor_sync(0xffffffffu, v, off);
    if (lane == 0) d_SQ[b][r] = 0.5f * v;
}

// ---------------------------------------------------------------------------
// cost: C[i][j] = 0.5||a_i||^2 + 0.5||b_j||^2 - a_i . b_j  (K=64)
// 64x64 tile, 4x4/thread; 5 matrices via blockIdx.z. No transposes.
// ---------------------------------------------------------------------------
__global__ __launch_bounds__(256) void k_cost() {
    __shared__ __align__(16) float sA[64 * 68];   // [kk][row]
    __shared__ __align__(16) float sB[64 * 68];   // [kk][col]
    const int z = blockIdx.z;
    const int ai = cAi[z], bi = cBi[z];
    const float* A = d_P[ai];
    const float* B = d_P[bi];
    int i0 = blockIdx.y * 64, j0 = blockIdx.x * 64;
    int tid = threadIdx.x, ty = tid >> 4, tx = tid & 15;

#pragma unroll
    for (int i = 0; i < 16; i++) {
        int e = tid + i * 256;
        int r = e >> 6, c = e & 63;
        sA[c * 68 + r] = A[(i0 + r) * DOUT + c];
        sB[c * 68 + r] = B[(j0 + r) * DOUT + c];
    }
    __syncthreads();

    float acc[4][4];
#pragma unroll
    for (int i = 0; i < 4; i++)
#pragma unroll
        for (int j = 0; j < 4; j++) acc[i][j] = 0.f;

#pragma unroll
    for (int kk = 0; kk < 64; kk++) {
        float4 a = *reinterpret_cast<const float4*>(&sA[kk * 68 + ty * 4]);
        float4 b = *reinterpret_cast<const float4*>(&sB[kk * 68 + tx * 4]);
        float av[4] = {a.x, a.y, a.z, a.w};
        float bv[4] = {b.x, b.y, b.z, b.w};
#pragma unroll
        for (int i = 0; i < 4; i++)
#pragma unroll
            for (int j = 0; j < 4; j++) acc[i][j] = fmaf(av[i], bv[j], acc[i][j]);
    }

    float sqa[4], sqb[4];
#pragma unroll
    for (int i = 0; i < 4; i++) sqa[i] = d_SQ[ai][i0 + ty * 4 + i];
#pragma unroll
    for (int j = 0; j < 4; j++) sqb[j] = d_SQ[bi][j0 + tx * 4 + j];

    float* Cm = d_C[z];
#pragma unroll
    for (int i = 0; i < 4; i++)
#pragma unroll
        for (int j = 0; j < 4; j++) {
            Cm[(size_t)(i0 + ty * 4 + i) * NPTS + j0 + tx * 4 + j] =
                sqa[i] + sqb[j] - acc[i][j];
        }
}

// ---------------------------------------------------------------------------
// zero ping-pong potential buffers + column counters
// ---------------------------------------------------------------------------
__global__ void k_init() {
    int e = blockIdx.x * blockDim.x + threadIdx.x;
    if (e < 2 * 7 * NPTS) (&d_pot[0][0][0])[e] = 0.f;
    if (e < 32) (&g_cnt[0][0])[e] = 0u;
}

// ---------------------------------------------------------------------------
// One Sinkhorn scan step.
// Blocks 0..127: COLUMN mode — g-updates for Cxy1/Cxy2 on the row-major
//   matrix. 2 mats x 16 col-chunks (128 cols) x 4 row-slabs (512 rows).
//   Per-lane float4 online LSE over 64 rows/warp, smem combine, slab partial
//   to global, last slab block (atomic counter) finalizes 128 columns.
// Blocks 128..1407: ROW mode — R11-verbatim (dense streaming / V-skip with
//   margin 30, SKIP_START 20) on matrices 0..4.
// f_i = eps*(ln N - ln2 * LSE2_j[(vin_j - C_ij)*log2e/eps])
// ---------------------------------------------------------------------------
__global__ __launch_bounds__(256) void k_step(int cur, float eps, int avg,
                                              int fin, int mode) {
    __shared__ __align__(16) float sg[NPTS];
    __shared__ float sdrift[NCHUNK];
    __shared__ __align__(16) float4 wm[8][32];
    __shared__ __align__(16) float4 ws[8][32];
    __shared__ unsigned s_old;

    const int blk = blockIdx.x;
    const int nxt = cur ^ 1;
    const float pscale = LOG2E / eps;
    const float nscale = -pscale;
    const float c2u = eps * LN2;                   // log2-units -> C-units
    const int wid = threadIdx.x >> 5, lane = threadIdx.x & 31;

    if (blk < COLBLKS) {
        // ===================== column mode =====================
        const int cm = blk >> 6;               // 0 -> Cxy1, 1 -> Cxy2
        const int rem = blk & 63;
        const int chunk = rem >> 2;            // 0..15 (128 cols)
        const int slab  = rem & 3;             // 0..3  (512 rows)
        const int vinSlot = 3 + 2 * cm;        // f_xy slot
        const int outSlot = 4 + 2 * cm;        // g_xy slot
        const float* __restrict__ vin = d_pot[cur][vinSlot];
        const float* __restrict__ Cm = d_C[3 + cm];

        // stage this slab's f window (scaled)
        for (int j = threadIdx.x; j < 512; j += 256)
            sg[j] = vin[slab * 512 + j] * pscale;
        __syncthreads();

        const int colg = chunk * 128 + lane * 4;
        const int rbase = wid * 64;            // rows in slab for this warp
        float4 m4 = make_float4(-3.4e38f, -3.4e38f, -3.4e38f, -3.4e38f);
        float4 s4 = make_float4(0.f, 0.f, 0.f, 0.f);
#pragma unroll 1
        for (int r0 = 0; r0 < 64; r0 += 8) {
            float4 t[8];
            float4 mc = make_float4(-3.4e38f, -3.4e38f, -3.4e38f, -3.4e38f);
#pragma unroll
            for (int k = 0; k < 8; k++) {
                const int rl = rbase + r0 + k;
                const size_t rr = (size_t)(slab * 512 + rl);
                float4 c = *reinterpret_cast<const float4*>(Cm + rr * NPTS + colg);
                float fv = sg[rl];
                float4 tt;
                tt.x = fmaf(c.x, nscale, fv);
                tt.y = fmaf(c.y, nscale, fv);
                tt.z = fmaf(c.z, nscale, fv);
                tt.w = fmaf(c.w, nscale, fv);
                t[k] = tt;
                mc.x = fmaxf(mc.x, tt.x); mc.y = fmaxf(mc.y, tt.y);
                mc.z = fmaxf(mc.z, tt.z); mc.w = fmaxf(mc.w, tt.w);
            }
            float4 mn;
            mn.x = fmaxf(m4.x, mc.x); mn.y = fmaxf(m4.y, mc.y);
            mn.z = fmaxf(m4.z, mc.z); mn.w = fmaxf(m4.w, mc.w);
            s4.x *= ex2f(m4.x - mn.x); s4.y *= ex2f(m4.y - mn.y);
            s4.z *= ex2f(m4.z - mn.z); s4.w *= ex2f(m4.w - mn.w);
#pragma unroll
            for (int k = 0; k < 8; k++) {
                s4.x += ex2f(t[k].x - mn.x);
                s4.y += ex2f(t[k].y - mn.y);
                s4.z += ex2f(t[k].z - mn.z);
                s4.w += ex2f(t[k].w - mn.w);
            }
            m4 = mn;
        }
        wm[wid][lane] = m4;
        ws[wid][lane] = s4;
        __syncthreads();

        if (wid == 0) {
            float4 M = wm[0][lane], S = ws[0][lane];
#pragma unroll
            for (int w = 1; w < 8; w++) {
                float4 mo = wm[w][lane], so = ws[w][lane];
                float4 mn;
                mn.x = fmaxf(M.x, mo.x); mn.y = fmaxf(M.y, mo.y);
                mn.z = fmaxf(M.z, mo.z); mn.w = fmaxf(M.w, mo.w);
                S.x = S.x * ex2f(M.x - mn.x) + so.x * ex2f(mo.x - mn.x);
                S.y = S.y * ex2f(M.y - mn.y) + so.y * ex2f(mo.y - mn.y);
                S.z = S.z * ex2f(M.z - mn.z) + so.z * ex2f(mo.z - mn.z);
                S.w = S.w * ex2f(M.w - mn.w) + so.w * ex2f(mo.w - mn.w);
                M = mn;
            }
            __stcg(reinterpret_cast<float4*>(&d_pm[cm][chunk][slab][lane * 4]), M);
            __stcg(reinterpret_cast<float4*>(&d_ps[cm][chunk][slab][lane * 4]), S);
        }
        __syncthreads();
        __threadfence();
        if (threadIdx.x == 0)
            s_old = atomicAdd(&g_cnt[cm][chunk], 1u);
        __syncthreads();

        if ((s_old & 3u) == 3u) {
            // last slab block of this chunk this step: finalize 128 columns
            __threadfence();
            const int t = threadIdx.x;
            if (t < 128) {
                const int col = chunk * 128 + t;
                float M = __ldcg(&d_pm[cm][chunk][0][t]);
                float S = __ldcg(&d_ps[cm][chunk][0][t]);
#pragma unroll
                for (int sbi = 1; sbi < 4; sbi++) {
                    float mo = __ldcg(&d_pm[cm][chunk][sbi][t]);
                    float so = __ldcg(&d_ps[cm][chunk][sbi][t]);
                    float mn = fmaxf(M, mo);
                    S = S * ex2f(M - mn) + so * ex2f(mo - mn);
                    M = mn;
                }
                float g = eps * (LN_N - (M + lg2f(S)) * LN2);
                if (avg) g = 0.5f * (d_pot[cur][outSlot][col] + g);
                float* outp = fin ? &d_potF[outSlot][col]
                                  : &d_pot[nxt][outSlot][col];
                *outp = g;
            }
        }
        return;
    }

    // ===================== row mode (R11-verbatim) =====================
    const int idx = blk - COLBLKS;
    const int pp = idx >> 8;                       // 256 blocks per pass
    const int sub = idx & 255;                     // 8 rows each
    const int vinSlot = cVinRow[pp];
    const float* __restrict__ vin  = d_pot[cur][vinSlot];
    const float* __restrict__ favg = d_pot[cur][cOutRow[pp]];
    float* __restrict__ out = fin ? d_potF[cOutRow[pp]] : d_pot[nxt][cOutRow[pp]];
    const float* __restrict__ Cm = d_C[pp];

    // stage vin * (log2e/eps) into shared
    {
        const float4* vin4 = reinterpret_cast<const float4*>(vin);
        float4* sg4s = reinterpret_cast<float4*>(sg);
        for (int j = threadIdx.x; j < NPTS / 4; j += 256) {
            float4 v = vin4[j];
            v.x *= pscale; v.y *= pscale; v.z *= pscale; v.w *= pscale;
            sg4s[j] = v;
        }
    }

    // snapshot raw vin slice for next step's drift (exclusive 8-elem slice)
    if (mode >= 1 && threadIdx.x < 8)
        d_prev[cur][pp][sub * 8 + threadIdx.x] = vin[sub * 8 + threadIdx.x];

    // per-chunk drift vs previous step's vin (C units)
    if (mode == 2) {
        const float4* vin4 = reinterpret_cast<const float4*>(vin);
        const float4* prv4 = reinterpret_cast<const float4*>(d_prev[cur ^ 1][pp]);
        for (int cc = wid; cc < NCHUNK; cc += 8) {
            float4 v = vin4[cc * 32 + lane];
            float4 p = prv4[cc * 32 + lane];
            float d = fmaxf(fmaxf(v.x - p.x, v.y - p.y),
                            fmaxf(v.z - p.z, v.w - p.w));
#pragma unroll
            for (int off = 16; off > 0; off >>= 1)
                d = fmaxf(d, __shfl_xor_sync(0xffffffffu, d, off));
            if (lane == 0) sdrift[cc] = d;
        }
    }
    __syncthreads();

    const float4* sg4 = reinterpret_cast<const float4*>(sg);
    const int row = sub * 8 + wid;
    const float4* __restrict__ Crow4 =
        reinterpret_cast<const float4*>(Cm + (size_t)row * NPTS);

    float m, s;

    if (mode == 0) {
        // ---------------- plain streaming (proven fastest dense path) ------
        float4 xv[8];
        float m1 = -3.4e38f;
#pragma unroll
        for (int k = 0; k < 8; k++) {
            float4 c = Crow4[k * 32 + lane];
            float4 g = sg4[k * 32 + lane];
            float4 t;
            t.x = fmaf(c.x, nscale, g.x);
            t.y = fmaf(c.y, nscale, g.y);
            t.z = fmaf(c.z, nscale, g.z);
            t.w = fmaf(c.w, nscale, g.w);
            xv[k] = t;
            m1 = fmaxf(m1, fmaxf(fmaxf(t.x, t.y), fmaxf(t.z, t.w)));
        }
        float s1 = 0.f;
#pragma unroll
        for (int k = 0; k < 8; k++)
            s1 += ex2f(xv[k].x - m1) + ex2f(xv[k].y - m1)
                + ex2f(xv[k].z - m1) + ex2f(xv[k].w - m1);

        float m2 = -3.4e38f;
#pragma unroll
        for (int k = 0; k < 8; k++) {
            float4 c = Crow4[256 + k * 32 + lane];
            float4 g = sg4[256 + k * 32 + lane];
            float4 t;
            t.x = fmaf(c.x, nscale, g.x);
            t.y = fmaf(c.y, nscale, g.y);
            t.z = fmaf(c.z, nscale, g.z);
            t.w = fmaf(c.w, nscale, g.w);
            xv[k] = t;
            m2 = fmaxf(m2, fmaxf(fmaxf(t.x, t.y), fmaxf(t.z, t.w)));
        }
        float s2 = 0.f;
#pragma unroll
        for (int k = 0; k < 8; k++)
            s2 += ex2f(xv[k].x - m2) + ex2f(xv[k].y - m2)
                + ex2f(xv[k].z - m2) + ex2f(xv[k].w - m2);

        m = fmaxf(m1, m2);
        s = s1 * ex2f(m1 - m) + s2 * ex2f(m2 - m);
    } else {
        // ---------------- V-maintained modes: 16 x 128-col chunks ---------
        float Vc = 0.f;
        float ub = -3.4e38f;
        if (mode == 2 && lane < NCHUNK) {
            Vc = d_V[pp][row][lane] - sdrift[lane];
            ub = -Vc * pscale;
        }

        int c1 = 0;
        if (mode == 2) {
            float av = ub; int bi = lane;
#pragma unroll
            for (int off = 16; off > 0; off >>= 1) {
                float vo = __shfl_xor_sync(0xffffffffu, av, off);
                int   io = __shfl_xor_sync(0xffffffffu, bi, off);
                if (vo > av || (vo == av && io < bi)) { av = vo; bi = io; }
            }
            c1 = bi;
        }

        float mglob;
        {
            float4 cc4 = Crow4[c1 * 32 + lane];
            float4 gg = sg4[c1 * 32 + lane];
            float4 t;
            t.x = fmaf(cc4.x, nscale, gg.x);
            t.y = fmaf(cc4.y, nscale, gg.y);
            t.z = fmaf(cc4.z, nscale, gg.z);
            t.w = fmaf(cc4.w, nscale, gg.w);
            float mc = fmaxf(fmaxf(t.x, t.y), fmaxf(t.z, t.w));
            float mw = mc;
#pragma unroll
            for (int off = 16; off > 0; off >>= 1)
                mw = fmaxf(mw, __shfl_xor_sync(0xffffffffu, mw, off));
            mglob = mw;
            m = mc;
            s = ex2f(t.x - m) + ex2f(t.y - m) + ex2f(t.z - m) + ex2f(t.w - m);
            if (lane == c1) Vc = -mw * c2u;
        }

#pragma unroll 1
        for (int c = 0; c < NCHUNK; ++c) {
            if (c == c1) continue;
            if (mode == 2) {
                float ubc = __shfl_sync(0xffffffffu, ub, c);
                if (ubc < mglob - SKIP_MARGIN) continue;
            }
            float4 cc4 = Crow4[c * 32 + lane];
            float4 gg = sg4[c * 32 + lane];
            float4 t;
            t.x = fmaf(cc4.x, nscale, gg.x);
            t.y = fmaf(cc4.y, nscale, gg.y);
            t.z = fmaf(cc4.z, nscale, gg.z);
            t.w = fmaf(cc4.w, nscale, gg.w);
            float mc = fmaxf(fmaxf(t.x, t.y), fmaxf(t.z, t.w));
            float mw = mc;
#pragma unroll
            for (int off = 16; off > 0; off >>= 1)
                mw = fmaxf(mw, __shfl_xor_sync(0xffffffffu, mw, off));
            if (lane == c) Vc = -mw * c2u;
            float mn = fmaxf(m, mw);
            s = s * ex2f(m - mn)
              + ex2f(t.x - mn) + ex2f(t.y - mn)
              + ex2f(t.z - mn) + ex2f(t.w - mn);
            m = mn;
        }

        if (lane < NCHUNK)
            d_V[pp][row][lane] = Vc;
    }

    // warp LSE combine
#pragma unroll
    for (int off = 16; off > 0; off >>= 1) {
        float mo = __shfl_xor_sync(0xffffffffu, m, off);
        float so = __shfl_xor_sync(0xffffffffu, s, off);
        float mn = fmaxf(m, mo);
        s = s * ex2f(m - mn) + so * ex2f(mo - mn);
        m = mn;
    }

    if (lane == 0) {
        float ft = eps * (LN_N - (m + lg2f(s)) * LN2);
        out[row] = avg ? 0.5f * (favg[row] + ft) : ft;
    }
}

// ---------------------------------------------------------------------------
// dist1 = <a, f_xy1 - f_xx> + <b, g_xy1 - g_y1y1>, dist2 analogous.
// out = sigmoid(10 * (dist2 - dist1))
// ---------------------------------------------------------------------------
__global__ void k_reduce(float* out) {
    __shared__ float s1h[256], s2h[256];
    int t = threadIdx.x;
    float a1 = 0.f, a2 = 0.f;
    for (int i = t; i < NPTS; i += 256) {
        float fxx = d_potF[0][i];
        a1 += (d_potF[3][i] - fxx) + (d_potF[4][i] - d_potF[1][i]);
        a2 += (d_potF[5][i] - fxx) + (d_potF[6][i] - d_potF[2][i]);
    }
    s1h[t] = a1;
    s2h[t] = a2;
    __syncthreads();
    for (int off = 128; off > 0; off >>= 1) {
        if (t < off) { s1h[t] += s1h[t + off]; s2h[t] += s2h[t + off]; }
        __syncthreads();
    }
    if (t == 0) {
        const float inv = 1.0f / (float)NPTS;
        float dist1 = s1h[0] * inv;
        float dist2 = s2h[0] * inv;
        float z = 10.0f * (dist2 - dist1);
        out[0] = 1.0f / (1.0f + expf(-z));
    }
}

// ---------------------------------------------------------------------------
// Launcher (graph-capturable: kernel launches only)
// ---------------------------------------------------------------------------
extern "C" void kernel_launch(void* const* d_in, const int* in_sizes, int n_in,
                              void* d_out, int out_size) {
    (void)in_sizes; (void)n_in; (void)out_size;
    const float* dX = (const float*)d_in[0];
    const float* s1 = (const float*)d_in[1];
    const float* s2 = (const float*)d_in[2];
    const float* W  = (const float*)d_in[3];
    const float* bb = (const float*)d_in[4];
    float* out = (float*)d_out;

    k_transposeW<<<(DIN * DOUT + 255) / 256, 256>>>(W);
    k_predict<<<dim3(NPTS / 64, 3), 256>>>(dX, s1, s2, bb);
    k_sqnorm<<<3 * NPTS / 8, 256>>>();
    k_cost<<<dim3(32, 32, 5), 256>>>();
    k_init<<<(2 * 7 * NPTS + 255) / 256, 256>>>();

    // epsilon schedule (geomloss-style), computed in double, cast to float
    const double eps0 = 32.0;
    const double epsf = pow(0.05, 2.0);
    const double ratio = pow(0.9, 2.0);
    int n = (int)ceil(log(epsf / eps0) / log(ratio));   // 45
    float sched[64];
    int cnt = 0;
    for (int k = 0; k <= n; k++) {
        double v = eps0 * pow(ratio, (double)k);
        if (v < epsf) v = epsf;
        sched[cnt++] = (float)v;
    }
    sched[cnt++] = (float)epsf;                          // cnt = 47

    for (int k = 0; k < cnt; k++) {
        int mode = (k < SKIP_START) ? 0 : (k == SKIP_START ? 1 : 2);
        k_step<<<GRIDX, 256>>>(k & 1, sched[k], 1, 0, mode);
    }

    // final differentiable update at eps_f (no averaging, write final arrays)
    k_step<<<GRIDX, 256>>>(cnt & 1, (float)epsf, 0, 1, 2);

    k_reduce<<<1, 256>>>(out);
}

// round 17
// speedup vs baseline: 1.4098x; 1.0150x over previous
#include <cuda_runtime.h>
#include <math.h>

#define NPTS 2048
#define DIN  768
#define DOUT 64
#define NMAT 5
#define NCHUNK 16                      // 128-column chunks per row
#define LN_N   7.624618986159398f      // ln(2048)
#define LOG2E  1.4426950408889634f
#define LN2    0.6931471805599453f
#define SKIP_MARGIN 30.0f              // R11-proven
#define SKIP_START 20                  // R11-proven

#define COLBLKS 128                    // 2 mats * 16 chunks * 4 slabs
#define ROWBLKS (5 * 256)              // 5 row passes, 8 rows/block
#define GRIDX   (COLBLKS + ROWBLKS)    // 1408

#define COST_SMEM (2 * 64 * 132 * 4)   // 67584 bytes dynamic smem for k_cost

// ---------------------------------------------------------------------------
// Device scratch (static globals — no allocation in kernel_launch)
// ---------------------------------------------------------------------------
__device__ __align__(16) float d_Wt[DIN * DOUT];             // W^T: [768][64]
__device__ __align__(16) float d_P[3][NPTS * DOUT];          // pd, p1, p2
__device__ __align__(16) float d_Pt[3][DOUT][NPTS];          // k-major copies
__device__ __align__(16) float d_SQ[3][NPTS];                // 0.5*||row||^2
__device__ __align__(16) float d_C[NMAT][(size_t)NPTS * NPTS];
// 0:Cxx 1:C11 2:C22 3:Cxy1 4:Cxy2   (80 MB — fits L2, stays resident)
__device__ __align__(16) float d_pot[2][7][NPTS];            // ping-pong potentials
// slots: 0:f_xx 1:f_11 2:f_22 3:f_xy1 4:g_xy1 5:f_xy2 6:g_xy2
__device__ __align__(16) float d_potF[7][NPTS];              // final potentials
__device__ __align__(16) float d_V[5][NPTS][NCHUNK];         // row-pass chunk bounds
__device__ __align__(16) float d_prev[2][5][NPTS];           // vin snapshots (2-buf)
// column-pass slab partials: [mat(2)][chunk(16)][slab(4)][col(128)]
__device__ __align__(16) float d_pm[2][16][4][128];
__device__ __align__(16) float d_ps[2][16][4][128];
__device__ unsigned g_cnt[2][16];                            // last-block counters

__constant__ int cAi[5] = {0, 1, 2, 0, 0};
__constant__ int cBi[5] = {0, 1, 2, 1, 2};
// row passes 0..4 read d_C[pass]; vin/out potential slots:
__constant__ int cVinRow[5] = {0, 1, 2, 4, 6};
__constant__ int cOutRow[5] = {0, 1, 2, 3, 5};

__device__ __forceinline__ float ex2f(float x) {
    float r; asm("ex2.approx.ftz.f32 %0, %1;" : "=f"(r) : "f"(x)); return r;
}
__device__ __forceinline__ float lg2f(float x) {
    float r; asm("lg2.approx.f32 %0, %1;" : "=f"(r) : "f"(x)); return r;
}

// ---------------------------------------------------------------------------
// W transpose:  Wt[j][k] = W[k][j]
// ---------------------------------------------------------------------------
__global__ void k_transposeW(const float* __restrict__ W) {
    int e = blockIdx.x * blockDim.x + threadIdx.x;
    if (e < DIN * DOUT) {
        int j = e / DOUT, k = e % DOUT;
        d_Wt[e] = W[k * DIN + j];
    }
}

// ---------------------------------------------------------------------------
// P transpose:  Pt[mat][k][row] = P[mat][row][k]  (k-major copies for k_cost)
// ---------------------------------------------------------------------------
__global__ void k_transposeP() {
    int e = blockIdx.x * blockDim.x + threadIdx.x;   // over 3*64*2048
    int mat = e >> 17;
    int r = e & 131071;
    int k = r >> 11;
    int row = r & 2047;
    d_Pt[mat][k][row] = d_P[mat][row * DOUT + k];
}

// ---------------------------------------------------------------------------
// predict: P = relu(X @ W^T + b). 64x64 tile / 256 threads.
// ---------------------------------------------------------------------------
__global__ __launch_bounds__(256) void k_predict(const float* __restrict__ X0,
                                                 const float* __restrict__ X1,
                                                 const float* __restrict__ X2,
                                                 const float* __restrict__ bias) {
    __shared__ __align__(16) float Xs[64 * 68];   // [kk][row]
    __shared__ __align__(16) float Ws[64 * 64];   // [kk][col]
    const float* X = (blockIdx.y == 0) ? X0 : (blockIdx.y == 1) ? X1 : X2;
    int rowBase = blockIdx.x * 64;
    int tid = threadIdx.x;
    int ty = tid >> 4, tx = tid & 15;

    float acc[4][4];
#pragma unroll
    for (int i = 0; i < 4; i++)
#pragma unroll
        for (int j = 0; j < 4; j++) acc[i][j] = 0.f;

    for (int k0 = 0; k0 < DIN; k0 += 64) {
#pragma unroll
        for (int i = 0; i < 16; i++) {
            int e = tid + i * 256;
            int r = e >> 6, c = e & 63;
            Xs[c * 68 + r] = X[(size_t)(rowBase + r) * DIN + k0 + c];
            Ws[r * 64 + c] = d_Wt[(k0 + r) * DOUT + c];
        }
        __syncthreads();
#pragma unroll
        for (int kk = 0; kk < 64; kk++) {
            float4 a = *reinterpret_cast<const float4*>(&Xs[kk * 68 + ty * 4]);
            float4 b = *reinterpret_cast<const float4*>(&Ws[kk * 64 + tx * 4]);
            float av[4] = {a.x, a.y, a.z, a.w};
            float bv[4] = {b.x, b.y, b.z, b.w};
#pragma unroll
            for (int i = 0; i < 4; i++)
#pragma unroll
                for (int j = 0; j < 4; j++) acc[i][j] = fmaf(av[i], bv[j], acc[i][j]);
        }
        __syncthreads();
    }

#pragma unroll
    for (int i = 0; i < 4; i++)
#pragma unroll
        for (int j = 0; j < 4; j++) {
            float v = acc[i][j] + bias[tx * 4 + j];
            v = fmaxf(v, 0.f);
            d_P[blockIdx.y][(rowBase + ty * 4 + i) * DOUT + tx * 4 + j] = v;
        }
}

// ---------------------------------------------------------------------------
// 0.5 * ||row||^2, one warp per row
// ---------------------------------------------------------------------------
__global__ void k_sqnorm() {
    int wid = threadIdx.x >> 5, lane = threadIdx.x & 31;
    int grow = blockIdx.x * 8 + wid;
    int b = grow >> 11, r = grow & (NPTS - 1);
    float v0 = d_P[b][r * DOUT + lane];
    float v1 = d_P[b][r * DOUT + 32 + lane];
    float v = v0 * v0 + v1 * v1;
#pragma unroll
    for (int off = 16; off > 0; off >>= 1)
        v += __shfl_xor_sync(0xffffffffu, v, off);
    if (lane == 0) d_SQ[b][r] = 0.5f * v;
}

// ---------------------------------------------------------------------------
// cost: C[i][j] = 0.5||a_i||^2 + 0.5||b_j||^2 - a_i . b_j  (K=64)
// v3: 128x128 tile, 8x8 per thread, K=64 single chunk, operands from the
// k-major d_Pt so smem fills are pure float4 (no scalar scatter, no K-chunk
// syncs). 4 LDS.128 per 64 FMA -> FMA-balanced. 67.6 KB dynamic smem.
// ---------------------------------------------------------------------------
__global__ __launch_bounds__(256) void k_cost() {
    extern __shared__ __align__(16) float smc[];
    float (*sA)[132] = reinterpret_cast<float (*)[132]>(smc);            // [64][132]
    float (*sB)[132] = reinterpret_cast<float (*)[132]>(smc + 64 * 132); // [64][132]
    const int z = blockIdx.z;
    const int ai = cAi[z], bi = cBi[z];
    const int i0 = blockIdx.y * 128, j0 = blockIdx.x * 128;
    const int tid = threadIdx.x;
    const int ty = tid >> 4, tx = tid & 15;

    // fill sA[kk][0..127] from Pt[ai][kk][i0..i0+127]  (2048 float4, 8/thread)
    {
        const float4* At = reinterpret_cast<const float4*>(&d_Pt[ai][0][0]);
        const float4* Bt = reinterpret_cast<const float4*>(&d_Pt[bi][0][0]);
#pragma unroll
        for (int i = 0; i < 8; i++) {
            int e4 = tid + i * 256;             // 0..2047
            int kk = e4 >> 5, c = e4 & 31;      // c = float4 within 128 cols
            float4 va = At[kk * (NPTS / 4) + (i0 >> 2) + c];
            float4 vb = Bt[kk * (NPTS / 4) + (j0 >> 2) + c];
            *reinterpret_cast<float4*>(&sA[kk][c * 4]) = va;
            *reinterpret_cast<float4*>(&sB[kk][c * 4]) = vb;
        }
    }
    __syncthreads();

    float acc[8][8];
#pragma unroll
    for (int i = 0; i < 8; i++)
#pragma unroll
        for (int j = 0; j < 8; j++) acc[i][j] = 0.f;

#pragma unroll 4
    for (int kk = 0; kk < 64; kk++) {
        float4 a0 = *reinterpret_cast<const float4*>(&sA[kk][ty * 8]);
        float4 a1 = *reinterpret_cast<const float4*>(&sA[kk][ty * 8 + 4]);
        float4 b0 = *reinterpret_cast<const float4*>(&sB[kk][tx * 8]);
        float4 b1 = *reinterpret_cast<const float4*>(&sB[kk][tx * 8 + 4]);
        float av[8] = {a0.x, a0.y, a0.z, a0.w, a1.x, a1.y, a1.z, a1.w};
        float bv[8] = {b0.x, b0.y, b0.z, b0.w, b1.x, b1.y, b1.z, b1.w};
#pragma unroll
        for (int i = 0; i < 8; i++)
#pragma unroll
            for (int j = 0; j < 8; j++)
                acc[i][j] = fmaf(av[i], bv[j], acc[i][j]);
    }

    float sqa[8], sqb[8];
#pragma unroll
    for (int i = 0; i < 8; i++) sqa[i] = d_SQ[ai][i0 + ty * 8 + i];
#pragma unroll
    for (int j = 0; j < 8; j++) sqb[j] = d_SQ[bi][j0 + tx * 8 + j];

    float* Cm = d_C[z];
#pragma unroll
    for (int i = 0; i < 8; i++) {
        float4 o0, o1;
        o0.x = sqa[i] + sqb[0] - acc[i][0];
        o0.y = sqa[i] + sqb[1] - acc[i][1];
        o0.z = sqa[i] + sqb[2] - acc[i][2];
        o0.w = sqa[i] + sqb[3] - acc[i][3];
        o1.x = sqa[i] + sqb[4] - acc[i][4];
        o1.y = sqa[i] + sqb[5] - acc[i][5];
        o1.z = sqa[i] + sqb[6] - acc[i][6];
        o1.w = sqa[i] + sqb[7] - acc[i][7];
        float* dst = Cm + (size_t)(i0 + ty * 8 + i) * NPTS + j0 + tx * 8;
        *reinterpret_cast<float4*>(dst) = o0;
        *reinterpret_cast<float4*>(dst + 4) = o1;
    }
}

// ---------------------------------------------------------------------------
// zero ping-pong potential buffers + column counters
// ---------------------------------------------------------------------------
__global__ void k_init() {
    int e = blockIdx.x * blockDim.x + threadIdx.x;
    if (e < 2 * 7 * NPTS) (&d_pot[0][0][0])[e] = 0.f;
    if (e < 32) (&g_cnt[0][0])[e] = 0u;
}

// ---------------------------------------------------------------------------
// One Sinkhorn scan step.  [R16-verbatim]
// Blocks 0..127: COLUMN mode — g-updates for Cxy1/Cxy2 on the row-major
//   matrix. 2 mats x 16 col-chunks (128 cols) x 4 row-slabs (512 rows).
//   Per-lane float4 online LSE over 64 rows/warp, smem combine, slab partial
//   to global, last slab block (atomic counter) finalizes 128 columns.
// Blocks 128..1407: ROW mode — R11-verbatim (dense streaming / V-skip with
//   margin 30, SKIP_START 20) on matrices 0..4.
// f_i = eps*(ln N - ln2 * LSE2_j[(vin_j - C_ij)*log2e/eps])
// ---------------------------------------------------------------------------
__global__ __launch_bounds__(256) void k_step(int cur, float eps, int avg,
                                              int fin, int mode) {
    __shared__ __align__(16) float sg[NPTS];
    __shared__ float sdrift[NCHUNK];
    __shared__ __align__(16) float4 wm[8][32];
    __shared__ __align__(16) float4 ws[8][32];
    __shared__ unsigned s_old;

    const int blk = blockIdx.x;
    const int nxt = cur ^ 1;
    const float pscale = LOG2E / eps;
    const float nscale = -pscale;
    const float c2u = eps * LN2;                   // log2-units -> C-units
    const int wid = threadIdx.x >> 5, lane = threadIdx.x & 31;

    if (blk < COLBLKS) {
        // ===================== column mode =====================
        const int cm = blk >> 6;               // 0 -> Cxy1, 1 -> Cxy2
        const int rem = blk & 63;
        const int chunk = rem >> 2;            // 0..15 (128 cols)
        const int slab  = rem & 3;             // 0..3  (512 rows)
        const int vinSlot = 3 + 2 * cm;        // f_xy slot
        const int outSlot = 4 + 2 * cm;        // g_xy slot
        const float* __restrict__ vin = d_pot[cur][vinSlot];
        const float* __restrict__ Cm = d_C[3 + cm];

        // stage this slab's f window (scaled)
        for (int j = threadIdx.x; j < 512; j += 256)
            sg[j] = vin[slab * 512 + j] * pscale;
        __syncthreads();

        const int colg = chunk * 128 + lane * 4;
        const int rbase = wid * 64;            // rows in slab for this warp
        float4 m4 = make_float4(-3.4e38f, -3.4e38f, -3.4e38f, -3.4e38f);
        float4 s4 = make_float4(0.f, 0.f, 0.f, 0.f);
#pragma unroll 1
        for (int r0 = 0; r0 < 64; r0 += 8) {
            float4 t[8];
            float4 mc = make_float4(-3.4e38f, -3.4e38f, -3.4e38f, -3.4e38f);
#pragma unroll
            for (int k = 0; k < 8; k++) {
                const int rl = rbase + r0 + k;
                const size_t rr = (size_t)(slab * 512 + rl);
                float4 c = *reinterpret_cast<const float4*>(Cm + rr * NPTS + colg);
                float fv = sg[rl];
                float4 tt;
                tt.x = fmaf(c.x, nscale, fv);
                tt.y = fmaf(c.y, nscale, fv);
                tt.z = fmaf(c.z, nscale, fv);
                tt.w = fmaf(c.w, nscale, fv);
                t[k] = tt;
                mc.x = fmaxf(mc.x, tt.x); mc.y = fmaxf(mc.y, tt.y);
                mc.z = fmaxf(mc.z, tt.z); mc.w = fmaxf(mc.w, tt.w);
            }
            float4 mn;
            mn.x = fmaxf(m4.x, mc.x); mn.y = fmaxf(m4.y, mc.y);
            mn.z = fmaxf(m4.z, mc.z); mn.w = fmaxf(m4.w, mc.w);
            s4.x *= ex2f(m4.x - mn.x); s4.y *= ex2f(m4.y - mn.y);
            s4.z *= ex2f(m4.z - mn.z); s4.w *= ex2f(m4.w - mn.w);
#pragma unroll
            for (int k = 0; k < 8; k++) {
                s4.x += ex2f(t[k].x - mn.x);
                s4.y += ex2f(t[k].y - mn.y);
                s4.z += ex2f(t[k].z - mn.z);
                s4.w += ex2f(t[k].w - mn.w);
            }
            m4 = mn;
        }
        wm[wid][lane] = m4;
        ws[wid][lane] = s4;
        __syncthreads();

        if (wid == 0) {
            float4 M = wm[0][lane], S = ws[0][lane];
#pragma unroll
            for (int w = 1; w < 8; w++) {
                float4 mo = wm[w][lane], so = ws[w][lane];
                float4 mn;
                mn.x = fmaxf(M.x, mo.x); mn.y = fmaxf(M.y, mo.y);
                mn.z = fmaxf(M.z, mo.z); mn.w = fmaxf(M.w, mo.w);
                S.x = S.x * ex2f(M.x - mn.x) + so.x * ex2f(mo.x - mn.x);
                S.y = S.y * ex2f(M.y - mn.y) + so.y * ex2f(mo.y - mn.y);
                S.z = S.z * ex2f(M.z - mn.z) + so.z * ex2f(mo.z - mn.z);
                S.w = S.w * ex2f(M.w - mn.w) + so.w * ex2f(mo.w - mn.w);
                M = mn;
            }
            __stcg(reinterpret_cast<float4*>(&d_pm[cm][chunk][slab][lane * 4]), M);
            __stcg(reinterpret_cast<float4*>(&d_ps[cm][chunk][slab][lane * 4]), S);
        }
        __syncthreads();
        __threadfence();
        if (threadIdx.x == 0)
            s_old = atomicAdd(&g_cnt[cm][chunk], 1u);
        __syncthreads();

        if ((s_old & 3u) == 3u) {
            // last slab block of this chunk this step: finalize 128 columns
            __threadfence();
            const int t = threadIdx.x;
            if (t < 128) {
                const int col = chunk * 128 + t;
                float M = __ldcg(&d_pm[cm][chunk][0][t]);
                float S = __ldcg(&d_ps[cm][chunk][0][t]);
#pragma unroll
                for (int sbi = 1; sbi < 4; sbi++) {
                    float mo = __ldcg(&d_pm[cm][chunk][sbi][t]);
                    float so = __ldcg(&d_ps[cm][chunk][sbi][t]);
                    float mn = fmaxf(M, mo);
                    S = S * ex2f(M - mn) + so * ex2f(mo - mn);
                    M = mn;
                }
                float g = eps * (LN_N - (M + lg2f(S)) * LN2);
                if (avg) g = 0.5f * (d_pot[cur][outSlot][col] + g);
                float* outp = fin ? &d_potF[outSlot][col]
                                  : &d_pot[nxt][outSlot][col];
                *outp = g;
            }
        }
        return;
    }

    // ===================== row mode (R11-verbatim) =====================
    const int idx = blk - COLBLKS;
    const int pp = idx >> 8;                       // 256 blocks per pass
    const int sub = idx & 255;                     // 8 rows each
    const int vinSlot = cVinRow[pp];
    const float* __restrict__ vin  = d_pot[cur][vinSlot];
    const float* __restrict__ favg = d_pot[cur][cOutRow[pp]];
    float* __restrict__ out = fin ? d_potF[cOutRow[pp]] : d_pot[nxt][cOutRow[pp]];
    const float* __restrict__ Cm = d_C[pp];

    // stage vin * (log2e/eps) into shared
    {
        const float4* vin4 = reinterpret_cast<const float4*>(vin);
        float4* sg4s = reinterpret_cast<float4*>(sg);
        for (int j = threadIdx.x; j < NPTS / 4; j += 256) {
            float4 v = vin4[j];
            v.x *= pscale; v.y *= pscale; v.z *= pscale; v.w *= pscale;
            sg4s[j] = v;
        }
    }

    // snapshot raw vin slice for next step's drift (exclusive 8-elem slice)
    if (mode >= 1 && threadIdx.x < 8)
        d_prev[cur][pp][sub * 8 + threadIdx.x] = vin[sub * 8 + threadIdx.x];

    // per-chunk drift vs previous step's vin (C units)
    if (mode == 2) {
        const float4* vin4 = reinterpret_cast<const float4*>(vin);
        const float4* prv4 = reinterpret_cast<const float4*>(d_prev[cur ^ 1][pp]);
        for (int cc = wid; cc < NCHUNK; cc += 8) {
            float4 v = vin4[cc * 32 + lane];
            float4 p = prv4[cc * 32 + lane];
            float d = fmaxf(fmaxf(v.x - p.x, v.y - p.y),
                            fmaxf(v.z - p.z, v.w - p.w));
#pragma unroll
            for (int off = 16; off > 0; off >>= 1)
                d = fmaxf(d, __shfl_xor_sync(0xffffffffu, d, off));
            if (lane == 0) sdrift[cc] = d;
        }
    }
    __syncthreads();

    const float4* sg4 = reinterpret_cast<const float4*>(sg);
    const int row = sub * 8 + wid;
    const float4* __restrict__ Crow4 =
        reinterpret_cast<const float4*>(Cm + (size_t)row * NPTS);

    float m, s;

    if (mode == 0) {
        // ---------------- plain streaming (proven fastest dense path) ------
        float4 xv[8];
        float m1 = -3.4e38f;
#pragma unroll
        for (int k = 0; k < 8; k++) {
            float4 c = Crow4[k * 32 + lane];
            float4 g = sg4[k * 32 + lane];
            float4 t;
            t.x = fmaf(c.x, nscale, g.x);
            t.y = fmaf(c.y, nscale, g.y);
            t.z = fmaf(c.z, nscale, g.z);
            t.w = fmaf(c.w, nscale, g.w);
            xv[k] = t;
            m1 = fmaxf(m1, fmaxf(fmaxf(t.x, t.y), fmaxf(t.z, t.w)));
        }
        float s1 = 0.f;
#pragma unroll
        for (int k = 0; k < 8; k++)
            s1 += ex2f(xv[k].x - m1) + ex2f(xv[k].y - m1)
                + ex2f(xv[k].z - m1) + ex2f(xv[k].w - m1);

        float m2 = -3.4e38f;
#pragma unroll
        for (int k = 0; k < 8; k++) {
            float4 c = Crow4[256 + k * 32 + lane];
            float4 g = sg4[256 + k * 32 + lane];
            float4 t;
            t.x = fmaf(c.x, nscale, g.x);
            t.y = fmaf(c.y, nscale, g.y);
            t.z = fmaf(c.z, nscale, g.z);
            t.w = fmaf(c.w, nscale, g.w);
            xv[k] = t;
            m2 = fmaxf(m2, fmaxf(fmaxf(t.x, t.y), fmaxf(t.z, t.w)));
        }
        float s2 = 0.f;
#pragma unroll
        for (int k = 0; k < 8; k++)
            s2 += ex2f(xv[k].x - m2) + ex2f(xv[k].y - m2)
                + ex2f(xv[k].z - m2) + ex2f(xv[k].w - m2);

        m = fmaxf(m1, m2);
        s = s1 * ex2f(m1 - m) + s2 * ex2f(m2 - m);
    } else {
        // ---------------- V-maintained modes: 16 x 128-col chunks ---------
        float Vc = 0.f;
        float ub = -3.4e38f;
        if (mode == 2 && lane < NCHUNK) {
            Vc = d_V[pp][row][lane] - sdrift[lane];
            ub = -Vc * pscale;
        }

        int c1 = 0;
        if (mode == 2) {
            float av = ub; int bi = lane;
#pragma unroll
            for (int off = 16; off > 0; off >>= 1) {
                float vo = __shfl_xor_sync(0xffffffffu, av, off);
                int   io = __shfl_xor_sync(0xffffffffu, bi, off);
                if (vo > av || (vo == av && io < bi)) { av = vo; bi = io; }
            }
            c1 = bi;
        }

        float mglob;
        {
            float4 cc4 = Crow4[c1 * 32 + lane];
            float4 gg = sg4[c1 * 32 + lane];
            float4 t;
            t.x = fmaf(cc4.x, nscale, gg.x);
            t.y = fmaf(cc4.y, nscale, gg.y);
            t.z = fmaf(cc4.z, nscale, gg.z);
            t.w = fmaf(cc4.w, nscale, gg.w);
            float mc = fmaxf(fmaxf(t.x, t.y), fmaxf(t.z, t.w));
            float mw = mc;
#pragma unroll
            for (int off = 16; off > 0; off >>= 1)
                mw = fmaxf(mw, __shfl_xor_sync(0xffffffffu, mw, off));
            mglob = mw;
            m = mc;
            s = ex2f(t.x - m) + ex2f(t.y - m) + ex2f(t.z - m) + ex2f(t.w - m);
            if (lane == c1) Vc = -mw * c2u;
        }

#pragma unroll 1
        for (int c = 0; c < NCHUNK; ++c) {
            if (c == c1) continue;
            if (mode == 2) {
                float ubc = __shfl_sync(0xffffffffu, ub, c);
                if (ubc < mglob - SKIP_MARGIN) continue;
            }
            float4 cc4 = Crow4[c * 32 + lane];
            float4 gg = sg4[c * 32 + lane];
            float4 t;
            t.x = fmaf(cc4.x, nscale, gg.x);
            t.y = fmaf(cc4.y, nscale, gg.y);
            t.z = fmaf(cc4.z, nscale, gg.z);
            t.w = fmaf(cc4.w, nscale, gg.w);
            float mc = fmaxf(fmaxf(t.x, t.y), fmaxf(t.z, t.w));
            float mw = mc;
#pragma unroll
            for (int off = 16; off > 0; off >>= 1)
                mw = fmaxf(mw, __shfl_xor_sync(0xffffffffu, mw, off));
            if (lane == c) Vc = -mw * c2u;
            float mn = fmaxf(m, mw);
            s = s * ex2f(m - mn)
              + ex2f(t.x - mn) + ex2f(t.y - mn)
              + ex2f(t.z - mn) + ex2f(t.w - mn);
            m = mn;
        }

        if (lane < NCHUNK)
            d_V[pp][row][lane] = Vc;
    }

    // warp LSE combine
#pragma unroll
    for (int off = 16; off > 0; off >>= 1) {
        float mo = __shfl_xor_sync(0xffffffffu, m, off);
        float so = __shfl_xor_sync(0xffffffffu, s, off);
        float mn = fmaxf(m, mo);
        s = s * ex2f(m - mn) + so * ex2f(mo - mn);
        m = mn;
    }

    if (lane == 0) {
        float ft = eps * (LN_N - (m + lg2f(s)) * LN2);
        out[row] = avg ? 0.5f * (favg[row] + ft) : ft;
    }
}

// ---------------------------------------------------------------------------
// dist1 = <a, f_xy1 - f_xx> + <b, g_xy1 - g_y1y1>, dist2 analogous.
// out = sigmoid(10 * (dist2 - dist1))
// ---------------------------------------------------------------------------
__global__ void k_reduce(float* out) {
    __shared__ float s1h[256], s2h[256];
    int t = threadIdx.x;
    float a1 = 0.f, a2 = 0.f;
    for (int i = t; i < NPTS; i += 256) {
        float fxx = d_potF[0][i];
        a1 += (d_potF[3][i] - fxx) + (d_potF[4][i] - d_potF[1][i]);
        a2 += (d_potF[5][i] - fxx) + (d_potF[6][i] - d_potF[2][i]);
    }
    s1h[t] = a1;
    s2h[t] = a2;
    __syncthreads();
    for (int off = 128; off > 0; off >>= 1) {
        if (t < off) { s1h[t] += s1h[t + off]; s2h[t] += s2h[t + off]; }
        __syncthreads();
    }
    if (t == 0) {
        const float inv = 1.0f / (float)NPTS;
        float dist1 = s1h[0] * inv;
        float dist2 = s2h[0] * inv;
        float z = 10.0f * (dist2 - dist1);
        out[0] = 1.0f / (1.0f + expf(-z));
    }
}

// ---------------------------------------------------------------------------
// Launcher (graph-capturable: kernel launches only)
// ---------------------------------------------------------------------------
extern "C" void kernel_launch(void* const* d_in, const int* in_sizes, int n_in,
                              void* d_out, int out_size) {
    (void)in_sizes; (void)n_in; (void)out_size;
    const float* dX = (const float*)d_in[0];
    const float* s1 = (const float*)d_in[1];
    const float* s2 = (const float*)d_in[2];
    const float* W  = (const float*)d_in[3];
    const float* bb = (const float*)d_in[4];
    float* out = (float*)d_out;

    cudaFuncSetAttribute(k_cost, cudaFuncAttributeMaxDynamicSharedMemorySize,
                         COST_SMEM);

    k_transposeW<<<(DIN * DOUT + 255) / 256, 256>>>(W);
    k_predict<<<dim3(NPTS / 64, 3), 256>>>(dX, s1, s2, bb);
    k_transposeP<<<(3 * DOUT * NPTS) / 256, 256>>>();
    k_sqnorm<<<3 * NPTS / 8, 256>>>();
    k_cost<<<dim3(16, 16, 5), 256, COST_SMEM>>>();
    k_init<<<(2 * 7 * NPTS + 255) / 256, 256>>>();

    // epsilon schedule (geomloss-style), computed in double, cast to float
    const double eps0 = 32.0;
    const double epsf = pow(0.05, 2.0);
    const double ratio = pow(0.9, 2.0);
    int n = (int)ceil(log(epsf / eps0) / log(ratio));   // 45
    float sched[64];
    int cnt = 0;
    for (int k = 0; k <= n; k++) {
        double v = eps0 * pow(ratio, (double)k);
        if (v < epsf) v = epsf;
        sched[cnt++] = (float)v;
    }
    sched[cnt++] = (float)epsf;                          // cnt = 47

    for (int k = 0; k < cnt; k++) {
        int mode = (k < SKIP_START) ? 0 : (k == SKIP_START ? 1 : 2);
        k_step<<<GRIDX, 256>>>(k & 1, sched[k], 1, 0, mode);
    }

    // final differentiable update at eps_f (no averaging, write final arrays)
    k_step<<<GRIDX, 256>>>(cnt & 1, (float)epsf, 0, 1, 2);

    k_reduce<<<1, 256>>>(out);
}